// round 2
// baseline (speedup 1.0000x reference)
#include <cuda_runtime.h>
#include <math.h>

#define Sc 2048
#define Dc 2048
#define SMK 2047
#define NT 1024
#define FULLM 0xffffffffu
#define IS2 0.70710678118654752440f

// ---------------- device scratch (no allocation allowed) ----------------
__device__ float g_ssq[8 * Sc];   // sum over d of dwt coeff^2
__device__ float g_pt[8 * Sc];    // per-token dot with w_val
__device__ float g_rhof[8 * Sc];  // final rho_f (normalized)
__device__ float g_kl[103];       // leray 103-tap circulant kernel

// ---------------- setup: leray conv taps --------------------------------
// leray = I - grad1(Jacobi50(div1(.))) : fixed circulant, support +-51.
// Response to a delta computed on a length-256 line (support never wraps).
__global__ void setup_kl_kernel() {
    __shared__ float p[256];
    int t = threadIdx.x;
    float bb = (t == 128) ? 1.0f : ((t == 129) ? -1.0f : 0.0f);  // div1(delta@128)
    p[t] = 0.0f;
    __syncthreads();
    for (int it = 0; it < 50; it++) {
        float l = (t > 0) ? p[t - 1] : 0.0f;
        float r = (t < 255) ? p[t + 1] : 0.0f;
        float v = 0.5f * (r + l - bb);
        __syncthreads();
        p[t] = v;
        __syncthreads();
    }
    if (t < 103) {
        int i = 77 + t;
        float del = (i == 128) ? 1.0f : 0.0f;
        g_kl[t] = del - (p[i + 1] - p[i]);   // kernel symmetric -> either orientation
    }
}

// ---------------- prep: DWT energies + per-token dots --------------------
// One CTA per (b, group of 8 seq rows). 256 threads x 2 float4 chunks = D.
__global__ void __launch_bounds__(256) prep_kernel(const float* __restrict__ x,
                                                   const float* __restrict__ wval) {
    int g = blockIdx.x;   // 0..255
    int b = blockIdx.y;   // 0..7
    int tid = threadIdx.x;
    const float4* xv = (const float4*)(x + ((size_t)b * Sc + 8 * (size_t)g) * Dc);
    const float4* wv = (const float4*)wval;

    float acc[16];
#pragma unroll
    for (int i = 0; i < 16; i++) acc[i] = 0.0f;

#pragma unroll
    for (int c = 0; c < 2; c++) {
        int c4 = tid + c * 256;
        float4 w4 = wv[c4];
        float xr[4][8];
#pragma unroll
        for (int r = 0; r < 8; r++) {
            float4 q = xv[r * 512 + c4];
            xr[0][r] = q.x; xr[1][r] = q.y; xr[2][r] = q.z; xr[3][r] = q.w;
        }
        float wc[4] = {w4.x, w4.y, w4.z, w4.w};
#pragma unroll
        for (int cc = 0; cc < 4; cc++) {
            const float* X = xr[cc];
            float w = wc[cc];
#pragma unroll
            for (int r = 0; r < 8; r++) acc[8 + r] += X[r] * w;
            float a10 = (X[0] + X[1]) * IS2, d10 = (X[0] - X[1]) * IS2;
            float a11 = (X[2] + X[3]) * IS2, d11 = (X[2] - X[3]) * IS2;
            float a12 = (X[4] + X[5]) * IS2, d12 = (X[4] - X[5]) * IS2;
            float a13 = (X[6] + X[7]) * IS2, d13 = (X[6] - X[7]) * IS2;
            float a20 = (a10 + a11) * IS2, d20 = (a10 - a11) * IS2;
            float a21 = (a12 + a13) * IS2, d21 = (a12 - a13) * IS2;
            float a3 = (a20 + a21) * IS2, d3 = (a20 - a21) * IS2;
            acc[0] += a3 * a3;   acc[1] += d3 * d3;
            acc[2] += d20 * d20; acc[3] += d21 * d21;
            acc[4] += d10 * d10; acc[5] += d11 * d11;
            acc[6] += d12 * d12; acc[7] += d13 * d13;
        }
    }
    // reduce 16 accumulators across the CTA
#pragma unroll
    for (int off = 16; off; off >>= 1)
#pragma unroll
        for (int j = 0; j < 16; j++) acc[j] += __shfl_xor_sync(FULLM, acc[j], off);

    __shared__ float sred[8 * 16];
    int lane = tid & 31, wid = tid >> 5;
    if (lane == 0)
#pragma unroll
        for (int j = 0; j < 16; j++) sred[wid * 16 + j] = acc[j];
    __syncthreads();
    if (tid < 16) {
        float s = 0.0f;
#pragma unroll
        for (int w = 0; w < 8; w++) s += sred[w * 16 + tid];
        int base = b * Sc;
        if (tid < 8) {
            int idx;
            if (tid == 0) idx = g;                       // approx
            else if (tid == 1) idx = 256 + g;            // level-3 detail
            else if (tid < 4) idx = 512 + 2 * g + (tid - 2);   // level-2
            else idx = 1024 + 4 * g + (tid - 4);         // level-1
            g_ssq[base + idx] = s;
        } else {
            g_pt[base + 8 * g + (tid - 8)] = s;
        }
    }
}

// ---------------- block reductions (1024 threads, 32 warps) --------------
__device__ __forceinline__ float bsum(float v, float* red) {
#pragma unroll
    for (int o = 16; o; o >>= 1) v += __shfl_xor_sync(FULLM, v, o);
    int lane = threadIdx.x & 31, wid = threadIdx.x >> 5;
    if (lane == 0) red[wid] = v;
    __syncthreads();
    if (wid == 0) {
        float t = red[lane];
#pragma unroll
        for (int o = 16; o; o >>= 1) t += __shfl_xor_sync(FULLM, t, o);
        if (lane == 0) red[0] = t;
    }
    __syncthreads();
    float r = red[0];
    __syncthreads();
    return r;
}

__device__ __forceinline__ float bmax(float v, float* red) {
#pragma unroll
    for (int o = 16; o; o >>= 1) v = fmaxf(v, __shfl_xor_sync(FULLM, v, o));
    int lane = threadIdx.x & 31, wid = threadIdx.x >> 5;
    if (lane == 0) red[wid] = v;
    __syncthreads();
    if (wid == 0) {
        float t = red[lane];
#pragma unroll
        for (int o = 16; o; o >>= 1) t = fmaxf(t, __shfl_xor_sync(FULLM, t, o));
        if (lane == 0) red[0] = t;
    }
    __syncthreads();
    float r = red[0];
    __syncthreads();
    return r;
}

// ---------------- leray as a 103-tap circular convolution ----------------
// Contract: caller synced, dst != src, dst not concurrently read. Ends synced.
__device__ __forceinline__ void conv_leray(float* __restrict__ dst,
                                           const float* __restrict__ src,
                                           const float* __restrict__ kl) {
    int i0 = 2 * threadIdx.x;
    int base = i0 - 51 + Sc;             // keep positive for & masking
    float acc0, acc1 = 0.0f;
    float v0 = src[base & SMK];
    acc0 = kl[0] * v0;
#pragma unroll
    for (int j = 1; j < 103; j++) {
        float val = src[(base + j) & SMK];
        acc0 += kl[j] * val;
        acc1 += kl[j - 1] * val;
    }
    float vl = src[(base + 103) & SMK];
    acc1 += kl[102] * vl;
    dst[i0] = acc0;
    dst[i0 + 1] = acc1;
    __syncthreads();
}

// ---------------- forward advect + normalize(abs+eps) --------------------
__device__ __forceinline__ float advect_norm(float* __restrict__ dst,
                                             const float* __restrict__ r,
                                             const float* __restrict__ uu,
                                             float dt, float kap, float* red) {
    int i0 = 2 * threadIdx.x, i1 = i0 + 1;
    int im1 = (i0 - 1) & SMK, ip2 = (i0 + 2) & SMK;
    float rm1 = r[im1], r0 = r[i0], rp1 = r[i1], rp2 = r[ip2];
    float um1 = uu[im1], u0 = uu[i0], u1 = uu[i1];
    float Fm1 = um1 > 0.0f ? um1 * rm1 : um1 * r0;
    float F0  = u0  > 0.0f ? u0 * r0   : u0 * rp1;
    float F1  = u1  > 0.0f ? u1 * rp1  : u1 * rp2;
    float a0 = r0 - dt * (F0 - Fm1);
    float a1 = rp1 - dt * (F1 - F0);
    if (kap != 0.0f) {
        a0 += kap * dt * (rp1 + rm1 - 2.0f * r0);
        a1 += kap * dt * (rp2 + r0 - 2.0f * rp1);
    }
    float y0 = fabsf(a0) + 1e-8f;
    float y1 = fabsf(a1) + 1e-8f;
    float Z = bsum(y0 + y1, red);
    dst[i0] = y0 / Z;
    dst[i1] = y1 / Z;
    __syncthreads();
    return Z;
}

// ---------------- backward of one advect+normalize step ------------------
// rbA holds r̄_{t+1} on entry. Accumulates ūp into ubA, optionally writes
// r̄_t into rbA. Returns this thread's dt̄ partial.
__device__ __forceinline__ float advect_bwd(const float* __restrict__ rt,
                                            const float* __restrict__ rnext,
                                            const float* __restrict__ uu,
                                            float dt, float Z,
                                            float* __restrict__ rbA,
                                            float* __restrict__ abA,
                                            float* __restrict__ ubA,
                                            bool write_rbar, float* red) {
    int i0 = 2 * threadIdx.x, i1 = i0 + 1;
    float dot = bsum(rbA[i0] * rnext[i0] + rbA[i1] * rnext[i1], red);

    int im1 = (i0 - 1) & SMK, ip2 = (i0 + 2) & SMK;
    float rm1 = rt[im1], r0 = rt[i0], rp1 = rt[i1], rp2 = rt[ip2];
    float um1 = uu[im1], u0 = uu[i0], u1 = uu[i1];
    float Fm1 = um1 > 0.0f ? um1 * rm1 : um1 * r0;
    float F0  = u0  > 0.0f ? u0 * r0   : u0 * rp1;
    float F1  = u1  > 0.0f ? u1 * rp1  : u1 * rp2;
    float a0 = r0 - dt * (F0 - Fm1);
    float a1 = rp1 - dt * (F1 - F0);
    float iZ = 1.0f / Z;
    float s0 = (a0 > 0.0f) ? 1.0f : ((a0 < 0.0f) ? -1.0f : 0.0f);
    float s1 = (a1 > 0.0f) ? 1.0f : ((a1 < 0.0f) ? -1.0f : 0.0f);
    float ab0 = (rbA[i0] - dot) * iZ * s0;
    float ab1 = (rbA[i1] - dot) * iZ * s1;
    float dtl = -(ab0 * (F0 - Fm1) + ab1 * (F1 - F0));
    abA[i0] = ab0;
    abA[i1] = ab1;
    __syncthreads();

    float abm1 = abA[im1];
    float abp2 = abA[ip2];
    float Fb_m1 = -dt * (abm1 - ab0);
    float Fb_0  = -dt * (ab0 - ab1);
    float Fb_1  = -dt * (ab1 - abp2);
    ubA[i0] += Fb_0 * (u0 > 0.0f ? r0 : rp1);
    ubA[i1] += Fb_1 * (u1 > 0.0f ? rp1 : rp2);
    if (write_rbar) {
        float nr0 = ab0 + (u0 > 0.0f ? Fb_0 * u0 : 0.0f) + (um1 > 0.0f ? 0.0f : Fb_m1 * um1);
        float nr1 = ab1 + (u1 > 0.0f ? Fb_1 * u1 : 0.0f) + (u0 > 0.0f ? 0.0f : Fb_0 * u0);
        rbA[i0] = nr0;
        rbA[i1] = nr1;
    }
    __syncthreads();
    return dtl;
}

// ---------------- one inner MPC gradient step ----------------------------
__device__ __forceinline__ void mpc_inner_step(const float* rho, const float* vA,
                                               float* uA, float* upA,
                                               float* r1A, float* r2A, float* r3A, float* r4A,
                                               float* rbA, float* abA, float* ubA,
                                               const float* klA, float* red) {
    int i0 = 2 * threadIdx.x, i1 = i0 + 1;
    conv_leray(upA, uA, klA);                       // up = leray(u)
    float au0 = fabsf(upA[i0]), au1 = fabsf(upA[i1]);
    float m = bmax(fmaxf(au0, au1), red);
    float nt = bsum(((au0 == m) ? 1.0f : 0.0f) + ((au1 == m) ? 1.0f : 0.0f), red);
    float dt = 0.4f / (m + 1e-8f);

    float z0 = advect_norm(r1A, rho, upA, dt, 0.0f, red);
    float z1 = advect_norm(r2A, r1A, upA, dt, 0.0f, red);
    float z2 = advect_norm(r3A, r2A, upA, dt, 0.0f, red);
    float z3 = advect_norm(r4A, r3A, upA, dt, 0.0f, red);

    ubA[i0] = 0.0f; ubA[i1] = 0.0f;
    rbA[i0] = 1.0f - vA[i0];                         // seed r̄4 = (1 - v)
    rbA[i1] = 1.0f - vA[i1];
    __syncthreads();

    float dtl = 0.0f;
    dtl += advect_bwd(r3A, r4A, upA, dt, z3, rbA, abA, ubA, true, red);
    dtl += advect_bwd(r2A, r3A, upA, dt, z2, rbA, abA, ubA, true, red);
    dtl += advect_bwd(r1A, r2A, upA, dt, z1, rbA, abA, ubA, true, red);
    dtl += advect_bwd(rho, r1A, upA, dt, z0, rbA, abA, ubA, false, red);

    float dtbar = bsum(dtl, red);
    float mbar = dtbar * (-dt * dt * 2.5f);          // d(dt)/dm = -dt^2/CFL
    float add0 = (au0 == m) ? mbar * ((upA[i0] > 0.0f) ? 1.0f : -1.0f) / nt : 0.0f;
    float add1 = (au1 == m) ? mbar * ((upA[i1] > 0.0f) ? 1.0f : -1.0f) / nt : 0.0f;
    ubA[i0] += add0; ubA[i1] += add1;
    __syncthreads();

    conv_leray(abA, ubA, klA);                       // ū = leray^T(ūp) = leray(ūp)
    uA[i0] -= 0.0125f * abA[i0];                     // u -= (INNER_LR / B) * ū
    uA[i1] -= 0.0125f * abA[i1];
    __syncthreads();
}

// ---------------- main simulation: one CTA per batch ---------------------
#define SIM_SMEM ((13 * 2048 + 104 + 32) * 4)

__global__ void __launch_bounds__(NT, 1) sim_kernel(const float* __restrict__ phi_g) {
    extern __shared__ float sm[];
    float* phiA = sm;
    float* vA   = sm + 1 * 2048;
    float* uA   = sm + 2 * 2048;
    float* upA  = sm + 3 * 2048;
    float* rhoA = sm + 4 * 2048;
    float* spA  = sm + 5 * 2048;
    float* r1A  = sm + 6 * 2048;
    float* r2A  = sm + 7 * 2048;
    float* r3A  = sm + 8 * 2048;
    float* r4A  = sm + 9 * 2048;
    float* rbA  = sm + 10 * 2048;
    float* abA  = sm + 11 * 2048;
    float* ubA  = sm + 12 * 2048;
    float* klA  = sm + 13 * 2048;        // 103 (+1 pad)
    float* red  = sm + 13 * 2048 + 104;  // 32

    int b = blockIdx.x;
    int tid = threadIdx.x;
    int i0 = 2 * tid, i1 = i0 + 1;

    phiA[i0] = phi_g[i0];
    phiA[i1] = phi_g[i1];
    if (tid < 103) klA[tid] = g_kl[tid];

    // rho = normalize(sqrt(ssq) (+eps))
    float y0 = sqrtf(g_ssq[b * Sc + i0]) + 1e-8f;
    float y1 = sqrtf(g_ssq[b * Sc + i1]) + 1e-8f;
    float Z0 = bsum(y0 + y1, red);
    rhoA[i0] = y0 / Z0;
    rhoA[i1] = y1 / Z0;

    // v: DWT of per-token signal
    r1A[i0] = g_pt[b * Sc + i0];
    r1A[i1] = g_pt[b * Sc + i1];
    __syncthreads();
    {   // level 1: 1024 pairs
        int j = tid;
        float e = r1A[2 * j], o = r1A[2 * j + 1];
        vA[1024 + j] = (e - o) * IS2;
        r2A[j] = (e + o) * IS2;
    }
    __syncthreads();
    if (tid < 512) {
        int j = tid;
        float e = r2A[2 * j], o = r2A[2 * j + 1];
        vA[512 + j] = (e - o) * IS2;
        r1A[j] = (e + o) * IS2;
    }
    __syncthreads();
    if (tid < 256) {
        int j = tid;
        float e = r1A[2 * j], o = r1A[2 * j + 1];
        vA[256 + j] = (e - o) * IS2;
        vA[j] = (e + o) * IS2;
    }
    __syncthreads();
    {
        float vy0 = 45.254833995939045f * fabsf(vA[i0]) + 1e-8f;  // sqrt(D)*|c| + eps
        float vy1 = 45.254833995939045f * fabsf(vA[i1]) + 1e-8f;
        float Zv = bsum(vy0 + vy1, red);
        vA[i0] = vy0 / Zv;
        vA[i1] = vy1 / Zv;
        __syncthreads();
    }

    float* rho = rhoA;
    float* spare = spA;

#pragma unroll 1
    for (int k = 0; k < 3; k++) {
        float kap = (k == 0) ? 0.01f : ((k == 1) ? 0.005f : 0.0f);

        // reaction (1 mirror-descent step), in place
        {
            float w0 = rho[i0] * expf(-0.1f * (phiA[i0] + logf(rho[i0])));
            float w1 = rho[i1] * expf(-0.1f * (phiA[i1] + logf(rho[i1])));
            w0 = fabsf(w0) + 1e-8f;
            w1 = fabsf(w1) + 1e-8f;
            float Zr = bsum(w0 + w1, red);
            rho[i0] = w0 / Zr;
            rho[i1] = w1 / Zr;
            __syncthreads();
        }

        // mpc: u = grad1(v); 5 inner gradient steps
        uA[i0] = vA[i1] - vA[i0];
        uA[i1] = vA[(i0 + 2) & SMK] - vA[i1];
        __syncthreads();
#pragma unroll 1
        for (int is = 0; is < 5; is++)
            mpc_inner_step(rho, vA, uA, upA, r1A, r2A, r3A, r4A, rbA, abA, ubA, klA, red);

        // u = leray(mpc result); dt; main advect with kappa
        conv_leray(upA, uA, klA);
        float a0 = fabsf(upA[i0]), a1 = fabsf(upA[i1]);
        float mm = bmax(fmaxf(a0, a1), red);
        float dt = 0.4f / (mm + 1e-8f);
        advect_norm(spare, rho, upA, dt, kap, red);
        float* tmp = rho; rho = spare; spare = tmp;
    }

    // rho_f = (rho + 0.1 v) / sum  (no abs, no eps)
    float f0 = rho[i0] + 0.1f * vA[i0];
    float f1 = rho[i1] + 0.1f * vA[i1];
    float Zf = bsum(f0 + f1, red);
    g_rhof[b * Sc + i0] = f0 / Zf;
    g_rhof[b * Sc + i1] = f1 / Zf;
}

// ---------------- epilogue: coeffs -> inverse DWT, fused -----------------
__global__ void __launch_bounds__(256) out_kernel(const float* __restrict__ bw,
                                                  float* __restrict__ out) {
    int g = blockIdx.x, b = blockIdx.y, tid = threadIdx.x;
    const float* rf = g_rhof + b * Sc;
    float rfA = rf[g];
    float rf3 = rf[256 + g];
    float rf2a = rf[512 + 2 * g], rf2b = rf[512 + 2 * g + 1];
    float rf1_0 = rf[1024 + 4 * g], rf1_1 = rf[1024 + 4 * g + 1];
    float rf1_2 = rf[1024 + 4 * g + 2], rf1_3 = rf[1024 + 4 * g + 3];

    const float C8 = 0.35355339059327376220f;  // 1/(2*sqrt(2))
    float cA = rfA * C8;
    float c3 = rf3 * C8;
    float c2arr[2] = {rf2a * 0.5f, rf2b * 0.5f};
    float c1arr[4] = {rf1_0 * IS2, rf1_1 * IS2, rf1_2 * IS2, rf1_3 * IS2};

    const float4* bw4 = (const float4*)bw;
    float4* o4 = (float4*)(out + ((size_t)b * Sc + 8 * (size_t)g) * Dc);
#pragma unroll
    for (int c = 0; c < 2; c++) {
        int c4 = tid + c * 256;
        float4 b0 = bw4[0 * 512 + c4];
        float4 b1 = bw4[1 * 512 + c4];
        float4 b2 = bw4[2 * 512 + c4];
        float4 b3 = bw4[3 * 512 + c4];
#pragma unroll
        for (int r = 0; r < 8; r++) {
            float s2 = (r < 4) ? 1.0f : -1.0f;
            float s1 = (((r >> 1) & 1) == 0) ? 1.0f : -1.0f;
            float s0 = ((r & 1) == 0) ? 1.0f : -1.0f;
            float k0 = cA;
            float k1 = s2 * c3;
            float k2 = s1 * c2arr[r >> 2];
            float k3 = s0 * c1arr[r >> 1];
            float4 o;
            o.x = k0 * b0.x + k1 * b1.x + k2 * b2.x + k3 * b3.x;
            o.y = k0 * b0.y + k1 * b1.y + k2 * b2.y + k3 * b3.y;
            o.z = k0 * b0.z + k1 * b1.z + k2 * b2.z + k3 * b3.z;
            o.w = k0 * b0.w + k1 * b1.w + k2 * b2.w + k3 * b3.w;
            o4[r * 512 + c4] = o;
        }
    }
}

// ---------------- launch --------------------------------------------------
extern "C" void kernel_launch(void* const* d_in, const int* in_sizes, int n_in,
                              void* d_out, int out_size) {
    const float* x    = (const float*)d_in[0];
    const float* wval = (const float*)d_in[1];
    const float* phi  = (const float*)d_in[2];
    const float* bw   = (const float*)d_in[3];
    float* out = (float*)d_out;

    cudaFuncSetAttribute(sim_kernel, cudaFuncAttributeMaxDynamicSharedMemorySize, SIM_SMEM);

    setup_kl_kernel<<<1, 256>>>();
    prep_kernel<<<dim3(256, 8), 256>>>(x, wval);
    sim_kernel<<<8, NT, SIM_SMEM>>>(phi);
    out_kernel<<<dim3(256, 8), 256>>>(bw, out);
}

// round 5
// speedup vs baseline: 1.7170x; 1.7170x over previous
#include <cuda_runtime.h>
#include <math.h>

#define Sc 2048
#define Dc 2048
#define NTS 512
#define FULLM 0xffffffffu
#define IS2 0.70710678118654752440f
#define LD 2176
#define HAL 64

// ---------------- device scratch ----------------------------------------
__device__ float g_ssq[8 * Sc];   // sum over d of dwt coeff^2
__device__ float g_pt[8 * Sc];    // per-token dot with w_val
__device__ float g_rhof[8 * Sc];  // final rho_f (normalized)
__device__ float g_kl[103];       // leray 103-tap circulant kernel

// ---------------- setup: leray conv taps ---------------------------------
__global__ void setup_kl_kernel() {
    __shared__ float p[256];
    int t = threadIdx.x;
    float bb = (t == 128) ? 1.0f : ((t == 129) ? -1.0f : 0.0f);  // div1(delta@128)
    p[t] = 0.0f;
    __syncthreads();
    for (int it = 0; it < 50; it++) {
        float l = (t > 0) ? p[t - 1] : 0.0f;
        float r = (t < 255) ? p[t + 1] : 0.0f;
        float v = 0.5f * (r + l - bb);
        __syncthreads();
        p[t] = v;
        __syncthreads();
    }
    if (t < 103) {
        int i = 77 + t;
        float del = (i == 128) ? 1.0f : 0.0f;
        g_kl[t] = del - (p[i + 1] - p[i]);   // symmetric kernel
    }
}

// ---------------- prep: DWT energies + per-token dots --------------------
__global__ void __launch_bounds__(256) prep_kernel(const float* __restrict__ x,
                                                   const float* __restrict__ wval) {
    int g = blockIdx.x;   // 0..255
    int b = blockIdx.y;   // 0..7
    int tid = threadIdx.x;
    const float4* xv = (const float4*)(x + ((size_t)b * Sc + 8 * (size_t)g) * Dc);
    const float4* wv = (const float4*)wval;

    float acc[16];
#pragma unroll
    for (int i = 0; i < 16; i++) acc[i] = 0.0f;

#pragma unroll
    for (int c = 0; c < 2; c++) {
        int c4 = tid + c * 256;
        float4 w4 = wv[c4];
        float xr[4][8];
#pragma unroll
        for (int r = 0; r < 8; r++) {
            float4 q = xv[r * 512 + c4];
            xr[0][r] = q.x; xr[1][r] = q.y; xr[2][r] = q.z; xr[3][r] = q.w;
        }
        float wc[4] = {w4.x, w4.y, w4.z, w4.w};
#pragma unroll
        for (int cc = 0; cc < 4; cc++) {
            const float* X = xr[cc];
            float w = wc[cc];
#pragma unroll
            for (int r = 0; r < 8; r++) acc[8 + r] += X[r] * w;
            float a10 = (X[0] + X[1]) * IS2, d10 = (X[0] - X[1]) * IS2;
            float a11 = (X[2] + X[3]) * IS2, d11 = (X[2] - X[3]) * IS2;
            float a12 = (X[4] + X[5]) * IS2, d12 = (X[4] - X[5]) * IS2;
            float a13 = (X[6] + X[7]) * IS2, d13 = (X[6] - X[7]) * IS2;
            float a20 = (a10 + a11) * IS2, d20 = (a10 - a11) * IS2;
            float a21 = (a12 + a13) * IS2, d21 = (a12 - a13) * IS2;
            float a3 = (a20 + a21) * IS2, d3 = (a20 - a21) * IS2;
            acc[0] += a3 * a3;   acc[1] += d3 * d3;
            acc[2] += d20 * d20; acc[3] += d21 * d21;
            acc[4] += d10 * d10; acc[5] += d11 * d11;
            acc[6] += d12 * d12; acc[7] += d13 * d13;
        }
    }
#pragma unroll
    for (int off = 16; off; off >>= 1)
#pragma unroll
        for (int j = 0; j < 16; j++) acc[j] += __shfl_xor_sync(FULLM, acc[j], off);

    __shared__ float sred[8 * 16];
    int lane = tid & 31, wid = tid >> 5;
    if (lane == 0)
#pragma unroll
        for (int j = 0; j < 16; j++) sred[wid * 16 + j] = acc[j];
    __syncthreads();
    if (tid < 16) {
        float s = 0.0f;
#pragma unroll
        for (int w = 0; w < 8; w++) s += sred[w * 16 + tid];
        int base = b * Sc;
        if (tid < 8) {
            int idx;
            if (tid == 0) idx = g;
            else if (tid == 1) idx = 256 + g;
            else if (tid < 4) idx = 512 + 2 * g + (tid - 2);
            else idx = 1024 + 4 * g + (tid - 4);
            g_ssq[base + idx] = s;
        } else {
            g_pt[base + 8 * g + (tid - 8)] = s;
        }
    }
}

// ---------------- small helpers ------------------------------------------
__device__ __forceinline__ float4 ld4(const float* p) { return *(const float4*)p; }
__device__ __forceinline__ void st4(float* p, float4 v) { *(float4*)p = v; }
__device__ __forceinline__ void st4h(float* A, int i0, float4 v) {
    *(float4*)(A + i0) = v;
    if (i0 < HAL) *(float4*)(A + i0 + Sc) = v;
    if (i0 >= Sc - HAL) *(float4*)(A + i0 - Sc) = v;
}
__device__ __forceinline__ void sth(float* A, int i, float v) {
    A[i] = v;
    if (i < HAL) A[i + Sc] = v;
    if (i >= Sc - HAL) A[i - Sc] = v;
}

// ---------------- block reductions (512 threads, 16 warps) ---------------
__device__ __forceinline__ float bsum(float v, float* red) {
#pragma unroll
    for (int o = 16; o; o >>= 1) v += __shfl_xor_sync(FULLM, v, o);
    int lane = threadIdx.x & 31, wid = threadIdx.x >> 5;
    if (lane == 0) red[wid] = v;
    __syncthreads();
    float s = 0.0f;
#pragma unroll
    for (int w = 0; w < 16; w++) s += red[w];
    __syncthreads();
    return s;
}

__device__ __forceinline__ float bmax(float v, float* red) {
#pragma unroll
    for (int o = 16; o; o >>= 1) v = fmaxf(v, __shfl_xor_sync(FULLM, v, o));
    int lane = threadIdx.x & 31, wid = threadIdx.x >> 5;
    if (lane == 0) red[wid] = v;
    __syncthreads();
    float m = red[0];
#pragma unroll
    for (int w = 1; w < 16; w++) m = fmaxf(m, red[w]);
    __syncthreads();
    return m;
}

// fused (max, tie-count) reduction
__device__ __forceinline__ float bmaxcnt(float m, float c, float* red, float* cnt_out) {
#pragma unroll
    for (int o = 16; o; o >>= 1) {
        float m2 = __shfl_xor_sync(FULLM, m, o);
        float c2 = __shfl_xor_sync(FULLM, c, o);
        if (m2 > m) { m = m2; c = c2; }
        else if (m2 == m) { c += c2; }
    }
    int lane = threadIdx.x & 31, wid = threadIdx.x >> 5;
    if (lane == 0) { red[wid] = m; red[16 + wid] = c; }
    __syncthreads();
    float M = red[0];
#pragma unroll
    for (int w = 1; w < 16; w++) M = fmaxf(M, red[w]);
    float C = 0.0f;
#pragma unroll
    for (int w = 0; w < 16; w++) C += (red[w] == M) ? red[16 + w] : 0.0f;
    __syncthreads();
    *cnt_out = C;
    return M;
}

// ---------------- leray: 81-tap conv, E=4, register rolling --------------
// Caller must be synced; ends synced. dst != src. src/dst haloed.
__device__ __forceinline__ void conv_leray(float* __restrict__ dst,
                                           const float* __restrict__ src,
                                           const float* __restrict__ kl) {
    int i0 = 4 * threadIdx.x;
    const float* S = src + i0 - 40;
    float4 cur = ld4(S);
    float a0 = 0.0f, a1 = 0.0f, a2 = 0.0f, a3 = 0.0f;
#pragma unroll
    for (int m = 0; m < 21; m++) {
        float4 nxt = ld4(S + 4 * m + 4);
        float4 k4 = ld4(kl + 4 * m);
        a0 += k4.x * cur.x + k4.y * cur.y + k4.z * cur.z + k4.w * cur.w;
        a1 += k4.x * cur.y + k4.y * cur.z + k4.z * cur.w + k4.w * nxt.x;
        a2 += k4.x * cur.z + k4.y * cur.w + k4.z * nxt.x + k4.w * nxt.y;
        a3 += k4.x * cur.w + k4.y * nxt.x + k4.z * nxt.y + k4.w * nxt.z;
        cur = nxt;
    }
    st4h(dst, i0, make_float4(a0, a1, a2, a3));
    __syncthreads();
}

// ---------------- forward advect + normalize -----------------------------
__device__ __forceinline__ float advect_norm4(float* __restrict__ dst,
                                              const float* __restrict__ r,
                                              const float* __restrict__ u,
                                              float dt, float kap, float* red) {
    int i0 = 4 * threadIdx.x;
    float4 r0 = ld4(r + i0), rp = ld4(r + i0 + 4);
    float4 u0 = ld4(u + i0);
    float rv[6] = {r[i0 - 1], r0.x, r0.y, r0.z, r0.w, rp.x};
    float uv[5] = {u[i0 - 1], u0.x, u0.y, u0.z, u0.w};
    float F[5];
#pragma unroll
    for (int k = 0; k < 5; k++)
        F[k] = uv[k] > 0.0f ? uv[k] * rv[k] : uv[k] * rv[k + 1];
    float y[4], part = 0.0f;
#pragma unroll
    for (int e = 0; e < 4; e++) {
        float a = rv[e + 1] - dt * (F[e + 1] - F[e]);
        if (kap != 0.0f)
            a += kap * dt * (rv[e + 2] + rv[e] - 2.0f * rv[e + 1]);
        y[e] = fabsf(a) + 1e-8f;
        part += y[e];
    }
    float Z = bsum(part, red);
    float iZ = 1.0f / Z;
    st4h(dst, i0, make_float4(y[0] * iZ, y[1] * iZ, y[2] * iZ, y[3] * iZ));
    __syncthreads();
    return Z;
}

// ---------------- backward of one advect+normalize step ------------------
__device__ __forceinline__ float advect_bwd4(const float* __restrict__ rt,
                                             const float* __restrict__ rn,
                                             const float* __restrict__ uu,
                                             float dt, float Z,
                                             float* __restrict__ rbA,
                                             float* __restrict__ abA,
                                             float* __restrict__ ubA,
                                             bool write_rbar, float* red) {
    int i0 = 4 * threadIdx.x;
    float4 rb4 = ld4(rbA + i0);
    float4 rn4 = ld4(rn + i0);
    float dot = bsum(rb4.x * rn4.x + rb4.y * rn4.y + rb4.z * rn4.z + rb4.w * rn4.w, red);

    float4 r0 = ld4(rt + i0), rp = ld4(rt + i0 + 4);
    float4 u0 = ld4(uu + i0);
    float rv[6] = {rt[i0 - 1], r0.x, r0.y, r0.z, r0.w, rp.x};
    float uv[5] = {uu[i0 - 1], u0.x, u0.y, u0.z, u0.w};
    float F[5];
#pragma unroll
    for (int k = 0; k < 5; k++)
        F[k] = uv[k] > 0.0f ? uv[k] * rv[k] : uv[k] * rv[k + 1];

    float rb[4] = {rb4.x, rb4.y, rb4.z, rb4.w};
    float iZ = 1.0f / Z;
    float ab[4], dtl = 0.0f;
#pragma unroll
    for (int e = 0; e < 4; e++) {
        float a = rv[e + 1] - dt * (F[e + 1] - F[e]);
        float s = (a > 0.0f) ? 1.0f : ((a < 0.0f) ? -1.0f : 0.0f);
        ab[e] = (rb[e] - dot) * iZ * s;
        dtl -= ab[e] * (F[e + 1] - F[e]);
    }
    st4h(abA, i0, make_float4(ab[0], ab[1], ab[2], ab[3]));
    __syncthreads();

    float abv[6] = {abA[i0 - 1], ab[0], ab[1], ab[2], ab[3], abA[i0 + 4]};
    float Fb[5];
#pragma unroll
    for (int k = 0; k < 5; k++)
        Fb[k] = -dt * (abv[k] - abv[k + 1]);

    float4 ub4 = ld4(ubA + i0);
    float ub[4] = {ub4.x, ub4.y, ub4.z, ub4.w};
#pragma unroll
    for (int e = 0; e < 4; e++)
        ub[e] += Fb[e + 1] * (uv[e + 1] > 0.0f ? rv[e + 1] : rv[e + 2]);
    st4h(ubA, i0, make_float4(ub[0], ub[1], ub[2], ub[3]));

    if (write_rbar) {
        float nr[4];
#pragma unroll
        for (int e = 0; e < 4; e++)
            nr[e] = ab[e] + (uv[e + 1] > 0.0f ? Fb[e + 1] * uv[e + 1] : 0.0f)
                          + (uv[e] > 0.0f ? 0.0f : Fb[e] * uv[e]);
        st4(rbA + i0, make_float4(nr[0], nr[1], nr[2], nr[3]));
    }
    __syncthreads();
    return dtl;
}

// ---------------- main simulation: one CTA per batch ---------------------
#define SIM_SMEM ((96 + 64 + 2048 + 2048 + 11 * LD) * 4)

__global__ void __launch_bounds__(NTS, 1) sim_kernel(const float* __restrict__ phi_g) {
    extern __shared__ float sm[];
    float* base = sm;
    float* klA = base;  base += 96;
    float* red = base;  base += 64;
    float* phiA = base; base += 2048;
    float* rbA = base;  base += 2048;
    float* vRaw = base;   base += LD;  float* vA   = vRaw + HAL;
    float* up0Raw = base; base += LD;  float* up0A = up0Raw + HAL;
    float* upRaw = base;  base += LD;  float* upA  = upRaw + HAL;
    float* rhoRaw = base; base += LD;  float* rhoA = rhoRaw + HAL;
    float* spRaw = base;  base += LD;  float* spA  = spRaw + HAL;
    float* r1Raw = base;  base += LD;  float* r1A  = r1Raw + HAL;
    float* r2Raw = base;  base += LD;  float* r2A  = r2Raw + HAL;
    float* r3Raw = base;  base += LD;  float* r3A  = r3Raw + HAL;
    float* r4Raw = base;  base += LD;  float* r4A  = r4Raw + HAL;
    float* abRaw = base;  base += LD;  float* abA  = abRaw + HAL;
    float* ubRaw = base;  base += LD;  float* ubA  = ubRaw + HAL;

    int b = blockIdx.x;
    int tid = threadIdx.x;
    int i0 = 4 * tid;

    // taps: center 81 of the 103, zero-padded to 84
    if (tid < 84) klA[tid] = (tid < 81) ? g_kl[tid + 11] : 0.0f;
    st4(phiA + i0, ld4(phi_g + i0));

    // rho = normalize(sqrt(ssq)+eps)
    {
        float4 s4 = ld4(g_ssq + b * Sc + i0);
        float y0 = sqrtf(s4.x) + 1e-8f, y1 = sqrtf(s4.y) + 1e-8f;
        float y2 = sqrtf(s4.z) + 1e-8f, y3 = sqrtf(s4.w) + 1e-8f;
        float Z = bsum(y0 + y1 + y2 + y3, red);
        float iZ = 1.0f / Z;
        st4h(rhoA, i0, make_float4(y0 * iZ, y1 * iZ, y2 * iZ, y3 * iZ));
    }

    // v = normalize(sqrt(D)*|dwt(pt)|+eps)
    st4(r1A + i0, ld4(g_pt + b * Sc + i0));
    __syncthreads();
#pragma unroll
    for (int s = 0; s < 2; s++) {           // level 1: 1024 pairs
        int j = 2 * tid + s;
        float e = r1A[2 * j], o = r1A[2 * j + 1];
        sth(vA, 1024 + j, (e - o) * IS2);
        r2A[j] = (e + o) * IS2;
    }
    __syncthreads();
    {                                       // level 2: 512 pairs
        float e = r2A[2 * tid], o = r2A[2 * tid + 1];
        sth(vA, 512 + tid, (e - o) * IS2);
        r1A[tid] = (e + o) * IS2;
    }
    __syncthreads();
    if (tid < 256) {                        // level 3: 256 pairs
        float e = r1A[2 * tid], o = r1A[2 * tid + 1];
        sth(vA, 256 + tid, (e - o) * IS2);
        sth(vA, tid, (e + o) * IS2);
    }
    __syncthreads();
    {
        float4 v4 = ld4(vA + i0);
        float y0 = 45.254833995939045f * fabsf(v4.x) + 1e-8f;
        float y1 = 45.254833995939045f * fabsf(v4.y) + 1e-8f;
        float y2 = 45.254833995939045f * fabsf(v4.z) + 1e-8f;
        float y3 = 45.254833995939045f * fabsf(v4.w) + 1e-8f;
        float Z = bsum(y0 + y1 + y2 + y3, red);
        float iZ = 1.0f / Z;
        st4h(vA, i0, make_float4(y0 * iZ, y1 * iZ, y2 * iZ, y3 * iZ));
        __syncthreads();
    }

    // up0 = leray(grad1(v)) — computed once (v is outer-invariant)
    {
        float4 v0 = ld4(vA + i0);
        float v4n = vA[i0 + 4];
        st4h(ubA, i0, make_float4(v0.y - v0.x, v0.z - v0.y, v0.w - v0.z, v4n - v0.w));
        __syncthreads();
        conv_leray(up0A, ubA, klA);
    }

    float* rho = rhoA;
    float* spare = spA;

#pragma unroll 1
    for (int k = 0; k < 3; k++) {
        float kap = (k == 0) ? 0.01f : ((k == 1) ? 0.005f : 0.0f);

        // reaction (1 mirror-descent step)
        {
            float4 rh = ld4(rho + i0);
            float4 ph = ld4(phiA + i0);
            float w0 = rh.x * expf(-0.1f * (ph.x + logf(rh.x)));
            float w1 = rh.y * expf(-0.1f * (ph.y + logf(rh.y)));
            float w2 = rh.z * expf(-0.1f * (ph.z + logf(rh.z)));
            float w3 = rh.w * expf(-0.1f * (ph.w + logf(rh.w)));
            w0 = fabsf(w0) + 1e-8f; w1 = fabsf(w1) + 1e-8f;
            w2 = fabsf(w2) + 1e-8f; w3 = fabsf(w3) + 1e-8f;
            float Z = bsum(w0 + w1 + w2 + w3, red);
            float iZ = 1.0f / Z;
            st4h(rho, i0, make_float4(w0 * iZ, w1 * iZ, w2 * iZ, w3 * iZ));
            __syncthreads();
        }

        // up <- up0 (full region incl. halo)
        for (int q = 4 * tid; q < LD; q += 4 * NTS)
            st4(upRaw + q, ld4(up0Raw + q));
        __syncthreads();

        // 5 inner MPC gradient steps, tracking up = leray(u) directly
#pragma unroll 1
        for (int is = 0; is < 5; is++) {
            float4 up4 = ld4(upA + i0);
            float a0 = fabsf(up4.x), a1 = fabsf(up4.y);
            float a2 = fabsf(up4.z), a3 = fabsf(up4.w);
            float lm = fmaxf(fmaxf(a0, a1), fmaxf(a2, a3));
            float lc = (a0 == lm ? 1.0f : 0.0f) + (a1 == lm ? 1.0f : 0.0f)
                     + (a2 == lm ? 1.0f : 0.0f) + (a3 == lm ? 1.0f : 0.0f);
            float nt;
            float m = bmaxcnt(lm, lc, red, &nt);
            float dt = 0.4f / (m + 1e-8f);

            float z0 = advect_norm4(r1A, rho, upA, dt, 0.0f, red);
            float z1 = advect_norm4(r2A, r1A, upA, dt, 0.0f, red);
            float z2 = advect_norm4(r3A, r2A, upA, dt, 0.0f, red);
            float z3 = advect_norm4(r4A, r3A, upA, dt, 0.0f, red);

            // seed backward
            st4h(ubA, i0, make_float4(0.0f, 0.0f, 0.0f, 0.0f));
            {
                float4 v4 = ld4(vA + i0);
                st4(rbA + i0, make_float4(1.0f - v4.x, 1.0f - v4.y, 1.0f - v4.z, 1.0f - v4.w));
            }
            __syncthreads();

            float dtl = 0.0f;
            dtl += advect_bwd4(r3A, r4A, upA, dt, z3, rbA, abA, ubA, true, red);
            dtl += advect_bwd4(r2A, r3A, upA, dt, z2, rbA, abA, ubA, true, red);
            dtl += advect_bwd4(r1A, r2A, upA, dt, z1, rbA, abA, ubA, true, red);
            dtl += advect_bwd4(rho, r1A, upA, dt, z0, rbA, abA, ubA, false, red);

            float dtbar = bsum(dtl, red);
            float mbar = dtbar * (-dt * dt * 2.5f);  // d(dt)/dm = -dt^2/CFL
            {
                float4 ub4 = ld4(ubA + i0);
                float inv_nt = mbar / nt;
                float add0 = (a0 == m) ? inv_nt * ((up4.x > 0.0f) ? 1.0f : -1.0f) : 0.0f;
                float add1 = (a1 == m) ? inv_nt * ((up4.y > 0.0f) ? 1.0f : -1.0f) : 0.0f;
                float add2 = (a2 == m) ? inv_nt * ((up4.z > 0.0f) ? 1.0f : -1.0f) : 0.0f;
                float add3 = (a3 == m) ? inv_nt * ((up4.w > 0.0f) ? 1.0f : -1.0f) : 0.0f;
                st4h(ubA, i0, make_float4(ub4.x + add0, ub4.y + add1,
                                          ub4.z + add2, ub4.w + add3));
            }
            __syncthreads();

            conv_leray(abA, ubA, klA);     // g  = leray(ūp)
            conv_leray(r1A, abA, klA);     // g2 = leray(g)
            {
                float4 u4 = ld4(upA + i0);
                float4 g4 = ld4(r1A + i0);
                // up -= (INNER_LR / B) * leray^2(ūp)
                st4h(upA, i0, make_float4(u4.x - 0.0125f * g4.x, u4.y - 0.0125f * g4.y,
                                          u4.z - 0.0125f * g4.z, u4.w - 0.0125f * g4.w));
            }
            __syncthreads();
        }

        // main advect with kappa; up already = leray(u_final)
        {
            float4 up4 = ld4(upA + i0);
            float lm = fmaxf(fmaxf(fabsf(up4.x), fabsf(up4.y)),
                             fmaxf(fabsf(up4.z), fabsf(up4.w)));
            float mm = bmax(lm, red);
            float dt = 0.4f / (mm + 1e-8f);
            advect_norm4(spare, rho, upA, dt, kap, red);
            float* tmp = rho; rho = spare; spare = tmp;
        }
    }

    // rho_f = (rho + 0.1 v) / sum
    {
        float4 rh = ld4(rho + i0);
        float4 v4 = ld4(vA + i0);
        float f0 = rh.x + 0.1f * v4.x, f1 = rh.y + 0.1f * v4.y;
        float f2 = rh.z + 0.1f * v4.z, f3 = rh.w + 0.1f * v4.w;
        float Z = bsum(f0 + f1 + f2 + f3, red);
        float iZ = 1.0f / Z;
        st4(g_rhof + b * Sc + i0, make_float4(f0 * iZ, f1 * iZ, f2 * iZ, f3 * iZ));
    }
}

// ---------------- epilogue: fused inverse DWT ----------------------------
__global__ void __launch_bounds__(256) out_kernel(const float* __restrict__ bw,
                                                  float* __restrict__ out) {
    int g = blockIdx.x, b = blockIdx.y, tid = threadIdx.x;
    const float* rf = g_rhof + b * Sc;
    float rfA = rf[g];
    float rf3 = rf[256 + g];
    float rf2a = rf[512 + 2 * g], rf2b = rf[512 + 2 * g + 1];
    float rf1_0 = rf[1024 + 4 * g], rf1_1 = rf[1024 + 4 * g + 1];
    float rf1_2 = rf[1024 + 4 * g + 2], rf1_3 = rf[1024 + 4 * g + 3];

    const float C8 = 0.35355339059327376220f;  // 1/(2*sqrt(2))
    float cA = rfA * C8;
    float c3 = rf3 * C8;
    float c2arr[2] = {rf2a * 0.5f, rf2b * 0.5f};
    float c1arr[4] = {rf1_0 * IS2, rf1_1 * IS2, rf1_2 * IS2, rf1_3 * IS2};

    const float4* bw4 = (const float4*)bw;
    float4* o4 = (float4*)(out + ((size_t)b * Sc + 8 * (size_t)g) * Dc);
#pragma unroll
    for (int c = 0; c < 2; c++) {
        int c4 = tid + c * 256;
        float4 b0 = bw4[0 * 512 + c4];
        float4 b1 = bw4[1 * 512 + c4];
        float4 b2 = bw4[2 * 512 + c4];
        float4 b3 = bw4[3 * 512 + c4];
#pragma unroll
        for (int r = 0; r < 8; r++) {
            float s2 = (r < 4) ? 1.0f : -1.0f;
            float s1 = (((r >> 1) & 1) == 0) ? 1.0f : -1.0f;
            float s0 = ((r & 1) == 0) ? 1.0f : -1.0f;
            float k0 = cA;
            float k1 = s2 * c3;
            float k2 = s1 * c2arr[r >> 2];
            float k3 = s0 * c1arr[r >> 1];
            float4 o;
            o.x = k0 * b0.x + k1 * b1.x + k2 * b2.x + k3 * b3.x;
            o.y = k0 * b0.y + k1 * b1.y + k2 * b2.y + k3 * b3.y;
            o.z = k0 * b0.z + k1 * b1.z + k2 * b2.z + k3 * b3.z;
            o.w = k0 * b0.w + k1 * b1.w + k2 * b2.w + k3 * b3.w;
            o4[r * 512 + c4] = o;
        }
    }
}

// ---------------- launch --------------------------------------------------
extern "C" void kernel_launch(void* const* d_in, const int* in_sizes, int n_in,
                              void* d_out, int out_size) {
    const float* x    = (const float*)d_in[0];
    const float* wval = (const float*)d_in[1];
    const float* phi  = (const float*)d_in[2];
    const float* bw   = (const float*)d_in[3];
    float* out = (float*)d_out;

    cudaFuncSetAttribute(sim_kernel, cudaFuncAttributeMaxDynamicSharedMemorySize, SIM_SMEM);

    setup_kl_kernel<<<1, 256>>>();
    prep_kernel<<<dim3(256, 8), 256>>>(x, wval);
    sim_kernel<<<8, NTS, SIM_SMEM>>>(phi);
    out_kernel<<<dim3(256, 8), 256>>>(bw, out);
}

// round 7
// speedup vs baseline: 1.8883x; 1.0997x over previous
#include <cuda_runtime.h>
#include <math.h>

#define Sc 2048
#define Dc 2048
#define NTS 512
#define FULLM 0xffffffffu
#define IS2 0.70710678118654752440f
#define HAL 72
#define LD 2192

// ---------------- device scratch ----------------------------------------
__device__ float g_ssq[8 * Sc];   // sum over d of dwt coeff^2
__device__ float g_pt[8 * Sc];    // per-token dot with w_val
__device__ float g_rhof[8 * Sc];  // final rho_f (normalized)
__device__ float g_kl[103];       // leray 103-tap circulant kernel
__device__ float g_kl2[132];      // 0.0125 * (kl conv kl), support +-64, padded

// ---------------- setup: leray conv taps + squared taps ------------------
__global__ void setup_kl_kernel() {
    __shared__ float p[256], klS[104];
    int t = threadIdx.x;
    float bb = (t == 128) ? 1.0f : ((t == 129) ? -1.0f : 0.0f);  // div1(delta@128)
    p[t] = 0.0f;
    __syncthreads();
    for (int it = 0; it < 50; it++) {
        float l = (t > 0) ? p[t - 1] : 0.0f;
        float r = (t < 255) ? p[t + 1] : 0.0f;
        float v = 0.5f * (r + l - bb);
        __syncthreads();
        p[t] = v;
        __syncthreads();
    }
    if (t < 103) {
        int i = 77 + t;
        float del = (i == 128) ? 1.0f : 0.0f;
        float v = del - (p[i + 1] - p[i]);   // symmetric kernel, disp = t-51
        g_kl[t] = v;
        klS[t] = v;
    }
    __syncthreads();
    if (t < 132) {
        float s = 0.0f;
        if (t < 129) {
            int d = t - 64;
            int lo = (d - 51 < -51) ? -51 : d - 51;
            int hi = (d + 51 > 51) ? 51 : d + 51;
            for (int a = lo; a <= hi; a++)
                s += klS[a + 51] * klS[d - a + 51];
            s *= 0.0125f;                     // INNER_LR / B folded in
        }
        g_kl2[t] = s;
    }
}

// ---------------- prep: DWT energies + per-token dots --------------------
__global__ void __launch_bounds__(256) prep_kernel(const float* __restrict__ x,
                                                   const float* __restrict__ wval) {
    int g = blockIdx.x;   // 0..255
    int b = blockIdx.y;   // 0..7
    int tid = threadIdx.x;
    const float4* xv = (const float4*)(x + ((size_t)b * Sc + 8 * (size_t)g) * Dc);
    const float4* wv = (const float4*)wval;

    float acc[16];
#pragma unroll
    for (int i = 0; i < 16; i++) acc[i] = 0.0f;

#pragma unroll
    for (int c = 0; c < 2; c++) {
        int c4 = tid + c * 256;
        float4 w4 = wv[c4];
        float xr[4][8];
#pragma unroll
        for (int r = 0; r < 8; r++) {
            float4 q = xv[r * 512 + c4];
            xr[0][r] = q.x; xr[1][r] = q.y; xr[2][r] = q.z; xr[3][r] = q.w;
        }
        float wc[4] = {w4.x, w4.y, w4.z, w4.w};
#pragma unroll
        for (int cc = 0; cc < 4; cc++) {
            const float* X = xr[cc];
            float w = wc[cc];
#pragma unroll
            for (int r = 0; r < 8; r++) acc[8 + r] += X[r] * w;
            float a10 = (X[0] + X[1]) * IS2, d10 = (X[0] - X[1]) * IS2;
            float a11 = (X[2] + X[3]) * IS2, d11 = (X[2] - X[3]) * IS2;
            float a12 = (X[4] + X[5]) * IS2, d12 = (X[4] - X[5]) * IS2;
            float a13 = (X[6] + X[7]) * IS2, d13 = (X[6] - X[7]) * IS2;
            float a20 = (a10 + a11) * IS2, d20 = (a10 - a11) * IS2;
            float a21 = (a12 + a13) * IS2, d21 = (a12 - a13) * IS2;
            float a3 = (a20 + a21) * IS2, d3 = (a20 - a21) * IS2;
            acc[0] += a3 * a3;   acc[1] += d3 * d3;
            acc[2] += d20 * d20; acc[3] += d21 * d21;
            acc[4] += d10 * d10; acc[5] += d11 * d11;
            acc[6] += d12 * d12; acc[7] += d13 * d13;
        }
    }
#pragma unroll
    for (int off = 16; off; off >>= 1)
#pragma unroll
        for (int j = 0; j < 16; j++) acc[j] += __shfl_xor_sync(FULLM, acc[j], off);

    __shared__ float sred[8 * 16];
    int lane = tid & 31, wid = tid >> 5;
    if (lane == 0)
#pragma unroll
        for (int j = 0; j < 16; j++) sred[wid * 16 + j] = acc[j];
    __syncthreads();
    if (tid < 16) {
        float s = 0.0f;
#pragma unroll
        for (int w = 0; w < 8; w++) s += sred[w * 16 + tid];
        int base = b * Sc;
        if (tid < 8) {
            int idx;
            if (tid == 0) idx = g;
            else if (tid == 1) idx = 256 + g;
            else if (tid < 4) idx = 512 + 2 * g + (tid - 2);
            else idx = 1024 + 4 * g + (tid - 4);
            g_ssq[base + idx] = s;
        } else {
            g_pt[base + 8 * g + (tid - 8)] = s;
        }
    }
}

// ---------------- small helpers ------------------------------------------
__device__ __forceinline__ float4 ld4(const float* p) { return *(const float4*)p; }
__device__ __forceinline__ void st4(float* p, float4 v) { *(float4*)p = v; }
__device__ __forceinline__ void st4h(float* A, int i0, float4 v) {
    *(float4*)(A + i0) = v;
    if (i0 < HAL) *(float4*)(A + i0 + Sc) = v;
    if (i0 >= Sc - HAL) *(float4*)(A + i0 - Sc) = v;
}
__device__ __forceinline__ void sth(float* A, int i, float v) {
    A[i] = v;
    if (i < HAL) A[i + Sc] = v;
    if (i >= Sc - HAL) A[i - Sc] = v;
}

// ------------- single-barrier reductions (512 thr, 16 warps) -------------
__device__ __forceinline__ float bsum1(float v, float* red, int& sl) {
#pragma unroll
    for (int o = 16; o; o >>= 1) v += __shfl_xor_sync(FULLM, v, o);
    int lane = threadIdx.x & 31, wid = threadIdx.x >> 5;
    if (lane == 0) red[sl * 16 + wid] = v;
    __syncthreads();
    float s = 0.0f;
    const float* rr = red + sl * 16;
#pragma unroll
    for (int w = 0; w < 16; w++) s += rr[w];
    sl ^= 1;
    return s;
}

__device__ __forceinline__ float bmax1(float v, float* mred) {
#pragma unroll
    for (int o = 16; o; o >>= 1) v = fmaxf(v, __shfl_xor_sync(FULLM, v, o));
    int lane = threadIdx.x & 31, wid = threadIdx.x >> 5;
    if (lane == 0) mred[wid] = v;
    __syncthreads();
    float m = mred[0];
#pragma unroll
    for (int w = 1; w < 16; w++) m = fmaxf(m, mred[w]);
    return m;
}

// fused (max, tie-count) reduction, one barrier
__device__ __forceinline__ float bmaxcnt1(float m, float c, float* mred, float* cnt_out) {
#pragma unroll
    for (int o = 16; o; o >>= 1) {
        float m2 = __shfl_xor_sync(FULLM, m, o);
        float c2 = __shfl_xor_sync(FULLM, c, o);
        if (m2 > m) { m = m2; c = c2; }
        else if (m2 == m) { c += c2; }
    }
    int lane = threadIdx.x & 31, wid = threadIdx.x >> 5;
    if (lane == 0) { mred[wid] = m; mred[16 + wid] = c; }
    __syncthreads();
    float M = mred[0];
#pragma unroll
    for (int w = 1; w < 16; w++) M = fmaxf(M, mred[w]);
    float C = 0.0f;
#pragma unroll
    for (int w = 0; w < 16; w++) C += (mred[w] == M) ? mred[16 + w] : 0.0f;
    *cnt_out = C;
    return M;
}

// ---------------- leray: 81-tap conv (init only) -------------------------
__device__ __forceinline__ void conv_leray(float* __restrict__ dst,
                                           const float* __restrict__ src,
                                           const float* __restrict__ kl) {
    int i0 = 4 * threadIdx.x;
    const float* S = src + i0 - 40;
    float4 cur = ld4(S);
    float a0 = 0.0f, a1 = 0.0f, a2 = 0.0f, a3 = 0.0f;
#pragma unroll
    for (int m = 0; m < 21; m++) {
        float4 nxt = ld4(S + 4 * m + 4);
        float4 k4 = ld4(kl + 4 * m);
        a0 += k4.x * cur.x + k4.y * cur.y + k4.z * cur.z + k4.w * cur.w;
        a1 += k4.x * cur.y + k4.y * cur.z + k4.z * cur.w + k4.w * nxt.x;
        a2 += k4.x * cur.z + k4.y * cur.w + k4.z * nxt.x + k4.w * nxt.y;
        a3 += k4.x * cur.w + k4.y * nxt.x + k4.z * nxt.y + k4.w * nxt.z;
        cur = nxt;
    }
    st4h(dst, i0, make_float4(a0, a1, a2, a3));
    __syncthreads();
}

// ------- fused: up -= (lr/B)*leray^2(ub), 132-tap conv, no barrier -------
__device__ __forceinline__ void conv2_update(float* __restrict__ up,
                                             const float* __restrict__ ub,
                                             const float* __restrict__ kl2) {
    int i0 = 4 * threadIdx.x;
    const float* S = ub + i0 - 64;
    float4 cur = ld4(S);
    float a0 = 0.0f, a1 = 0.0f, a2 = 0.0f, a3 = 0.0f;
#pragma unroll
    for (int m = 0; m < 33; m++) {
        float4 nxt = ld4(S + 4 * m + 4);
        float4 k4 = ld4(kl2 + 4 * m);
        a0 += k4.x * cur.x + k4.y * cur.y + k4.z * cur.z + k4.w * cur.w;
        a1 += k4.x * cur.y + k4.y * cur.z + k4.z * cur.w + k4.w * nxt.x;
        a2 += k4.x * cur.z + k4.y * cur.w + k4.z * nxt.x + k4.w * nxt.y;
        a3 += k4.x * cur.w + k4.y * nxt.x + k4.z * nxt.y + k4.w * nxt.z;
        cur = nxt;
    }
    float4 u = ld4(up + i0);
    st4h(up, i0, make_float4(u.x - a0, u.y - a1, u.z - a2, u.w - a3));
}

// ---- forward advect: store RAW y, one barrier, return Z -----------------
__device__ __forceinline__ float advect_fwd(float* __restrict__ dst,
                                            const float* __restrict__ r, float iZr,
                                            const float* __restrict__ u,
                                            float dt, float* red, int& sl) {
    int i0 = 4 * threadIdx.x;
    float4 r0 = ld4(r + i0);
    float rv[6] = {r[i0 - 1] * iZr, r0.x * iZr, r0.y * iZr, r0.z * iZr, r0.w * iZr,
                   r[i0 + 4] * iZr};
    float4 u0 = ld4(u + i0);
    float uv[5] = {u[i0 - 1], u0.x, u0.y, u0.z, u0.w};
    float F[5];
#pragma unroll
    for (int k = 0; k < 5; k++)
        F[k] = uv[k] > 0.0f ? uv[k] * rv[k] : uv[k] * rv[k + 1];
    float y[4], part = 0.0f;
#pragma unroll
    for (int e = 0; e < 4; e++) {
        y[e] = fabsf(rv[e + 1] - dt * (F[e + 1] - F[e])) + 1e-8f;
        part += y[e];
    }
    st4h(dst, i0, make_float4(y[0], y[1], y[2], y[3]));
    return bsum1(part, red, sl);   // barrier inside also publishes dst
}

// ---- final outer advect (with kappa), stores NORMALIZED -----------------
__device__ __forceinline__ void advect_final(float* __restrict__ dst,
                                             const float* __restrict__ r,  // normalized
                                             const float* __restrict__ u,
                                             float dt, float kap, float* red, int& sl) {
    int i0 = 4 * threadIdx.x;
    float4 r0 = ld4(r + i0);
    float rv[6] = {r[i0 - 1], r0.x, r0.y, r0.z, r0.w, r[i0 + 4]};
    float4 u0 = ld4(u + i0);
    float uv[5] = {u[i0 - 1], u0.x, u0.y, u0.z, u0.w};
    float F[5];
#pragma unroll
    for (int k = 0; k < 5; k++)
        F[k] = uv[k] > 0.0f ? uv[k] * rv[k] : uv[k] * rv[k + 1];
    float y[4], part = 0.0f;
#pragma unroll
    for (int e = 0; e < 4; e++) {
        float a = rv[e + 1] - dt * (F[e + 1] - F[e])
                + kap * dt * (rv[e + 2] + rv[e] - 2.0f * rv[e + 1]);
        y[e] = fabsf(a) + 1e-8f;
        part += y[e];
    }
    float Z = bsum1(part, red, sl);
    float iZ = 1.0f / Z;
    st4h(dst, i0, make_float4(y[0] * iZ, y[1] * iZ, y[2] * iZ, y[3] * iZ));
}

// ---- backward of one advect+normalize step: 2 barriers ------------------
__device__ __forceinline__ float advect_bwd(const float* __restrict__ rt, float iZt,
                                            const float* __restrict__ rn, float Zn,
                                            const float* __restrict__ u, float dt,
                                            float* __restrict__ rbA,
                                            float* __restrict__ abA,
                                            float* __restrict__ ubA,
                                            bool write_rbar, float* red, int& sl) {
    int i0 = 4 * threadIdx.x;
    float4 rb4 = ld4(rbA + i0);
    float4 rn4 = ld4(rn + i0);  // raw y_next
    float dotraw = bsum1(rb4.x * rn4.x + rb4.y * rn4.y + rb4.z * rn4.z + rb4.w * rn4.w,
                         red, sl);                     // BARRIER 1
    float iZn = 1.0f / Zn;
    float dot = dotraw * iZn;

    float4 r0 = ld4(rt + i0);
    float rv[6] = {rt[i0 - 1] * iZt, r0.x * iZt, r0.y * iZt, r0.z * iZt, r0.w * iZt,
                   rt[i0 + 4] * iZt};
    float4 u0 = ld4(u + i0);
    float uv[5] = {u[i0 - 1], u0.x, u0.y, u0.z, u0.w};
    float F[5];
#pragma unroll
    for (int k = 0; k < 5; k++)
        F[k] = uv[k] > 0.0f ? uv[k] * rv[k] : uv[k] * rv[k + 1];

    float rb[4] = {rb4.x, rb4.y, rb4.z, rb4.w};
    float ab[4], dtl = 0.0f;
#pragma unroll
    for (int e = 0; e < 4; e++) {
        float a = rv[e + 1] - dt * (F[e + 1] - F[e]);
        float s = (a > 0.0f) ? 1.0f : ((a < 0.0f) ? -1.0f : 0.0f);
        ab[e] = (rb[e] - dot) * iZn * s;
        dtl -= ab[e] * (F[e + 1] - F[e]);
    }
    st4h(abA, i0, make_float4(ab[0], ab[1], ab[2], ab[3]));
    __syncthreads();                                    // BARRIER 2

    float abv[6] = {abA[i0 - 1], ab[0], ab[1], ab[2], ab[3], abA[i0 + 4]};
    float Fb[5];
#pragma unroll
    for (int k = 0; k < 5; k++)
        Fb[k] = -dt * (abv[k] - abv[k + 1]);

    float4 ub4 = ld4(ubA + i0);
    float ub[4] = {ub4.x, ub4.y, ub4.z, ub4.w};
#pragma unroll
    for (int e = 0; e < 4; e++)
        ub[e] += Fb[e + 1] * (uv[e + 1] > 0.0f ? rv[e + 1] : rv[e + 2]);
    st4h(ubA, i0, make_float4(ub[0], ub[1], ub[2], ub[3]));

    if (write_rbar) {
        float nr[4];
#pragma unroll
        for (int e = 0; e < 4; e++)
            nr[e] = ab[e] + (uv[e + 1] > 0.0f ? Fb[e + 1] * uv[e + 1] : 0.0f)
                          + (uv[e] > 0.0f ? 0.0f : Fb[e] * uv[e]);
        st4(rbA + i0, make_float4(nr[0], nr[1], nr[2], nr[3]));
    }
    return dtl;   // no trailing barrier (next phase's reduction barrier orders)
}

// ---------------- main simulation: one CTA per batch ---------------------
#define SIM_SMEM ((4400 + 11 * LD) * 4)

__global__ void __launch_bounds__(NTS, 1) sim_kernel(const float* __restrict__ phi_g) {
    extern __shared__ float sm[];
    float* klA  = sm;          // 96  (81 taps pad 84)
    float* kl2A = sm + 96;     // 144 (132 taps)
    float* red  = sm + 240;    // 32 (2 slots x 16)
    float* mred = sm + 272;    // 32 (max + cnt)
    float* phiA = sm + 304;    // 2048
    float* rbA  = sm + 2352;   // 2048
    float* arr  = sm + 4400;   // 11 x LD haloed arrays
    float* vA   = arr + 0 * LD + HAL;
    float* up0A = arr + 1 * LD + HAL;
    float* upA  = arr + 2 * LD + HAL;
    float* rhoA = arr + 3 * LD + HAL;
    float* spA  = arr + 4 * LD + HAL;
    float* r1A  = arr + 5 * LD + HAL;
    float* r2A  = arr + 6 * LD + HAL;
    float* r3A  = arr + 7 * LD + HAL;
    float* r4A  = arr + 8 * LD + HAL;
    float* abA  = arr + 9 * LD + HAL;
    float* ubA  = arr + 10 * LD + HAL;

    int b = blockIdx.x;
    int tid = threadIdx.x;
    int i0 = 4 * tid;
    int sl = 0;

    if (tid < 84)  klA[tid]  = (tid < 81) ? g_kl[tid + 11] : 0.0f;
    if (tid < 132) kl2A[tid] = g_kl2[tid];
    st4(phiA + i0, ld4(phi_g + i0));

    // rho = normalize(sqrt(ssq)+eps)
    {
        float4 s4 = ld4(g_ssq + b * Sc + i0);
        float y0 = sqrtf(s4.x) + 1e-8f, y1 = sqrtf(s4.y) + 1e-8f;
        float y2 = sqrtf(s4.z) + 1e-8f, y3 = sqrtf(s4.w) + 1e-8f;
        float Z = bsum1(y0 + y1 + y2 + y3, red, sl);
        float iZ = 1.0f / Z;
        st4h(rhoA, i0, make_float4(y0 * iZ, y1 * iZ, y2 * iZ, y3 * iZ));
    }

    // v = normalize(sqrt(D)*|dwt(pt)|+eps)
    st4(r1A + i0, ld4(g_pt + b * Sc + i0));
    __syncthreads();
#pragma unroll
    for (int s = 0; s < 2; s++) {           // level 1
        int j = 2 * tid + s;
        float e = r1A[2 * j], o = r1A[2 * j + 1];
        sth(vA, 1024 + j, (e - o) * IS2);
        r2A[j] = (e + o) * IS2;
    }
    __syncthreads();
    {                                       // level 2
        float e = r2A[2 * tid], o = r2A[2 * tid + 1];
        sth(vA, 512 + tid, (e - o) * IS2);
        r1A[tid] = (e + o) * IS2;
    }
    __syncthreads();
    if (tid < 256) {                        // level 3
        float e = r1A[2 * tid], o = r1A[2 * tid + 1];
        sth(vA, 256 + tid, (e - o) * IS2);
        sth(vA, tid, (e + o) * IS2);
    }
    __syncthreads();
    {
        float4 v4 = ld4(vA + i0);
        float y0 = 45.254833995939045f * fabsf(v4.x) + 1e-8f;
        float y1 = 45.254833995939045f * fabsf(v4.y) + 1e-8f;
        float y2 = 45.254833995939045f * fabsf(v4.z) + 1e-8f;
        float y3 = 45.254833995939045f * fabsf(v4.w) + 1e-8f;
        float Z = bsum1(y0 + y1 + y2 + y3, red, sl);
        float iZ = 1.0f / Z;
        st4h(vA, i0, make_float4(y0 * iZ, y1 * iZ, y2 * iZ, y3 * iZ));
        __syncthreads();
    }

    // up0 = leray(grad1(v)) — outer-invariant
    {
        float4 v0 = ld4(vA + i0);
        float v4n = vA[i0 + 4];
        st4h(ubA, i0, make_float4(v0.y - v0.x, v0.z - v0.y, v0.w - v0.z, v4n - v0.w));
        __syncthreads();
        conv_leray(up0A, ubA, klA);
    }

    float* rho = rhoA;
    float* spare = spA;

#pragma unroll 1
    for (int k = 0; k < 3; k++) {
        float kap = (k == 0) ? 0.01f : ((k == 1) ? 0.005f : 0.0f);

        // reaction (1 mirror-descent step); stores normalized rho
        {
            float4 rh = ld4(rho + i0);
            float4 ph = ld4(phiA + i0);
            float w0 = fabsf(rh.x * expf(-0.1f * (ph.x + logf(rh.x)))) + 1e-8f;
            float w1 = fabsf(rh.y * expf(-0.1f * (ph.y + logf(rh.y)))) + 1e-8f;
            float w2 = fabsf(rh.z * expf(-0.1f * (ph.z + logf(rh.z)))) + 1e-8f;
            float w3 = fabsf(rh.w * expf(-0.1f * (ph.w + logf(rh.w)))) + 1e-8f;
            float Z = bsum1(w0 + w1 + w2 + w3, red, sl);
            float iZ = 1.0f / Z;
            st4h(rho, i0, make_float4(w0 * iZ, w1 * iZ, w2 * iZ, w3 * iZ));
        }

        // up <- up0 (full haloed range); copy is NOT own-aligned -> must fence
        for (int q = 4 * tid; q < LD; q += 4 * NTS)
            st4(arr + 2 * LD + q, ld4(arr + 1 * LD + q));
        __syncthreads();   // REQUIRED: reader below is offset by HAL from writer

        // 5 inner MPC gradient steps (up = leray(u) tracked directly)
#pragma unroll 1
        for (int is = 0; is < 5; is++) {
            float4 up4 = ld4(upA + i0);
            float a0 = fabsf(up4.x), a1 = fabsf(up4.y);
            float a2 = fabsf(up4.z), a3 = fabsf(up4.w);
            float lm = fmaxf(fmaxf(a0, a1), fmaxf(a2, a3));
            float lc = (a0 == lm ? 1.0f : 0.0f) + (a1 == lm ? 1.0f : 0.0f)
                     + (a2 == lm ? 1.0f : 0.0f) + (a3 == lm ? 1.0f : 0.0f);
            float nt;
            float m = bmaxcnt1(lm, lc, mred, &nt);          // 1 barrier
            float dt = 0.4f / (m + 1e-8f);

            float z0 = advect_fwd(r1A, rho, 1.0f, upA, dt, red, sl);
            float z1 = advect_fwd(r2A, r1A, 1.0f / z0, upA, dt, red, sl);
            float z2 = advect_fwd(r3A, r2A, 1.0f / z1, upA, dt, red, sl);
            float z3 = advect_fwd(r4A, r3A, 1.0f / z2, upA, dt, red, sl);

            // seed backward (own-thread writes only; next barrier orders)
            st4h(ubA, i0, make_float4(0.0f, 0.0f, 0.0f, 0.0f));
            {
                float4 v4 = ld4(vA + i0);
                st4(rbA + i0, make_float4(1.0f - v4.x, 1.0f - v4.y,
                                          1.0f - v4.z, 1.0f - v4.w));
            }

            float dtl = 0.0f;
            dtl += advect_bwd(r3A, 1.0f / z2, r4A, z3, upA, dt, rbA, abA, ubA, true,  red, sl);
            dtl += advect_bwd(r2A, 1.0f / z1, r3A, z2, upA, dt, rbA, abA, ubA, true,  red, sl);
            dtl += advect_bwd(r1A, 1.0f / z0, r2A, z1, upA, dt, rbA, abA, ubA, true,  red, sl);
            dtl += advect_bwd(rho, 1.0f,      r1A, z0, upA, dt, rbA, abA, ubA, false, red, sl);

            float dtbar = bsum1(dtl, red, sl);
            float mbar = dtbar * (-dt * dt * 2.5f);  // d(dt)/dm = -dt^2/CFL
            {
                float4 ub4 = ld4(ubA + i0);
                float inv_nt = mbar / nt;
                float add0 = (a0 == m) ? inv_nt * ((up4.x > 0.0f) ? 1.0f : -1.0f) : 0.0f;
                float add1 = (a1 == m) ? inv_nt * ((up4.y > 0.0f) ? 1.0f : -1.0f) : 0.0f;
                float add2 = (a2 == m) ? inv_nt * ((up4.z > 0.0f) ? 1.0f : -1.0f) : 0.0f;
                float add3 = (a3 == m) ? inv_nt * ((up4.w > 0.0f) ? 1.0f : -1.0f) : 0.0f;
                st4h(ubA, i0, make_float4(ub4.x + add0, ub4.y + add1,
                                          ub4.z + add2, ub4.w + add3));
            }
            __syncthreads();                    // publish ub before conv reads

            conv2_update(upA, ubA, kl2A);       // up -= (lr/B)*leray^2(ub)
            // no barrier: next reader of up is own-thread, then barriers
        }

        // main advect with kappa; up already = leray(u_final)
        {
            float4 up4 = ld4(upA + i0);
            float lm = fmaxf(fmaxf(fabsf(up4.x), fabsf(up4.y)),
                             fmaxf(fabsf(up4.z), fabsf(up4.w)));
            float mm = bmax1(lm, mred);         // 1 barrier (orders up too)
            float dt = 0.4f / (mm + 1e-8f);
            advect_final(spare, rho, upA, dt, kap, red, sl);
            float* tmp = rho; rho = spare; spare = tmp;
        }
    }

    // rho_f = (rho + 0.1 v) / sum
    {
        float4 rh = ld4(rho + i0);
        float4 v4 = ld4(vA + i0);
        float f0 = rh.x + 0.1f * v4.x, f1 = rh.y + 0.1f * v4.y;
        float f2 = rh.z + 0.1f * v4.z, f3 = rh.w + 0.1f * v4.w;
        float Z = bsum1(f0 + f1 + f2 + f3, red, sl);
        float iZ = 1.0f / Z;
        st4(g_rhof + b * Sc + i0, make_float4(f0 * iZ, f1 * iZ, f2 * iZ, f3 * iZ));
    }
}

// ---------------- epilogue: fused inverse DWT ----------------------------
__global__ void __launch_bounds__(256) out_kernel(const float* __restrict__ bw,
                                                  float* __restrict__ out) {
    int g = blockIdx.x, b = blockIdx.y, tid = threadIdx.x;
    const float* rf = g_rhof + b * Sc;
    float rfA = rf[g];
    float rf3 = rf[256 + g];
    float rf2a = rf[512 + 2 * g], rf2b = rf[512 + 2 * g + 1];
    float rf1_0 = rf[1024 + 4 * g], rf1_1 = rf[1024 + 4 * g + 1];
    float rf1_2 = rf[1024 + 4 * g + 2], rf1_3 = rf[1024 + 4 * g + 3];

    const float C8 = 0.35355339059327376220f;  // 1/(2*sqrt(2))
    float cA = rfA * C8;
    float c3 = rf3 * C8;
    float c2arr[2] = {rf2a * 0.5f, rf2b * 0.5f};
    float c1arr[4] = {rf1_0 * IS2, rf1_1 * IS2, rf1_2 * IS2, rf1_3 * IS2};

    const float4* bw4 = (const float4*)bw;
    float4* o4 = (float4*)(out + ((size_t)b * Sc + 8 * (size_t)g) * Dc);
#pragma unroll
    for (int c = 0; c < 2; c++) {
        int c4 = tid + c * 256;
        float4 b0 = bw4[0 * 512 + c4];
        float4 b1 = bw4[1 * 512 + c4];
        float4 b2 = bw4[2 * 512 + c4];
        float4 b3 = bw4[3 * 512 + c4];
#pragma unroll
        for (int r = 0; r < 8; r++) {
            float s2 = (r < 4) ? 1.0f : -1.0f;
            float s1 = (((r >> 1) & 1) == 0) ? 1.0f : -1.0f;
            float s0 = ((r & 1) == 0) ? 1.0f : -1.0f;
            float k0 = cA;
            float k1 = s2 * c3;
            float k2 = s1 * c2arr[r >> 2];
            float k3 = s0 * c1arr[r >> 1];
            float4 o;
            o.x = k0 * b0.x + k1 * b1.x + k2 * b2.x + k3 * b3.x;
            o.y = k0 * b0.y + k1 * b1.y + k2 * b2.y + k3 * b3.y;
            o.z = k0 * b0.z + k1 * b1.z + k2 * b2.z + k3 * b3.z;
            o.w = k0 * b0.w + k1 * b1.w + k2 * b2.w + k3 * b3.w;
            o4[r * 512 + c4] = o;
        }
    }
}

// ---------------- launch --------------------------------------------------
extern "C" void kernel_launch(void* const* d_in, const int* in_sizes, int n_in,
                              void* d_out, int out_size) {
    const float* x    = (const float*)d_in[0];
    const float* wval = (const float*)d_in[1];
    const float* phi  = (const float*)d_in[2];
    const float* bw   = (const float*)d_in[3];
    float* out = (float*)d_out;

    cudaFuncSetAttribute(sim_kernel, cudaFuncAttributeMaxDynamicSharedMemorySize, SIM_SMEM);

    setup_kl_kernel<<<1, 256>>>();
    prep_kernel<<<dim3(256, 8), 256>>>(x, wval);
    sim_kernel<<<8, NTS, SIM_SMEM>>>(phi);
    out_kernel<<<dim3(256, 8), 256>>>(bw, out);
}

// round 8
// speedup vs baseline: 2.0307x; 1.0754x over previous
#include <cuda_runtime.h>
#include <math.h>

#define Sc 2048
#define Dc 2048
#define NTS 512
#define FULLM 0xffffffffu
#define IS2 0.70710678118654752440f
#define HAL 72
#define LD 2192

// ---------------- device scratch ----------------------------------------
__device__ float g_ssq[8 * Sc];   // sum over d of dwt coeff^2
__device__ float g_pt[8 * Sc];    // per-token dot with w_val
__device__ float g_rhof[8 * Sc];  // final rho_f (normalized)
__device__ float g_kl[103];       // leray 103-tap circulant kernel
__device__ float g_kl2[132];      // 0.0125 * (kl conv kl), support +-64

// ---------------- setup: leray conv taps + squared taps ------------------
__global__ void setup_kl_kernel() {
    __shared__ float p[256], klS[104];
    int t = threadIdx.x;
    float bb = (t == 128) ? 1.0f : ((t == 129) ? -1.0f : 0.0f);  // div1(delta@128)
    p[t] = 0.0f;
    __syncthreads();
    for (int it = 0; it < 50; it++) {
        float l = (t > 0) ? p[t - 1] : 0.0f;
        float r = (t < 255) ? p[t + 1] : 0.0f;
        float v = 0.5f * (r + l - bb);
        __syncthreads();
        p[t] = v;
        __syncthreads();
    }
    if (t < 103) {
        int i = 77 + t;
        float del = (i == 128) ? 1.0f : 0.0f;
        float v = del - (p[i + 1] - p[i]);   // symmetric kernel, disp = t-51
        g_kl[t] = v;
        klS[t] = v;
    }
    __syncthreads();
    if (t < 132) {
        float s = 0.0f;
        if (t < 129) {
            int d = t - 64;
            int lo = (d - 51 < -51) ? -51 : d - 51;
            int hi = (d + 51 > 51) ? 51 : d + 51;
            for (int a = lo; a <= hi; a++)
                s += klS[a + 51] * klS[d - a + 51];
            s *= 0.0125f;                     // INNER_LR / B folded in
        }
        g_kl2[t] = s;
    }
}

// ---------------- prep: DWT energies + per-token dots --------------------
__global__ void __launch_bounds__(256) prep_kernel(const float* __restrict__ x,
                                                   const float* __restrict__ wval) {
    int g = blockIdx.x;   // 0..255
    int b = blockIdx.y;   // 0..7
    int tid = threadIdx.x;
    const float4* xv = (const float4*)(x + ((size_t)b * Sc + 8 * (size_t)g) * Dc);
    const float4* wv = (const float4*)wval;

    float acc[16];
#pragma unroll
    for (int i = 0; i < 16; i++) acc[i] = 0.0f;

#pragma unroll
    for (int c = 0; c < 2; c++) {
        int c4 = tid + c * 256;
        float4 w4 = wv[c4];
        float xr[4][8];
#pragma unroll
        for (int r = 0; r < 8; r++) {
            float4 q = xv[r * 512 + c4];
            xr[0][r] = q.x; xr[1][r] = q.y; xr[2][r] = q.z; xr[3][r] = q.w;
        }
        float wc[4] = {w4.x, w4.y, w4.z, w4.w};
#pragma unroll
        for (int cc = 0; cc < 4; cc++) {
            const float* X = xr[cc];
            float w = wc[cc];
#pragma unroll
            for (int r = 0; r < 8; r++) acc[8 + r] += X[r] * w;
            float a10 = (X[0] + X[1]) * IS2, d10 = (X[0] - X[1]) * IS2;
            float a11 = (X[2] + X[3]) * IS2, d11 = (X[2] - X[3]) * IS2;
            float a12 = (X[4] + X[5]) * IS2, d12 = (X[4] - X[5]) * IS2;
            float a13 = (X[6] + X[7]) * IS2, d13 = (X[6] - X[7]) * IS2;
            float a20 = (a10 + a11) * IS2, d20 = (a10 - a11) * IS2;
            float a21 = (a12 + a13) * IS2, d21 = (a12 - a13) * IS2;
            float a3 = (a20 + a21) * IS2, d3 = (a20 - a21) * IS2;
            acc[0] += a3 * a3;   acc[1] += d3 * d3;
            acc[2] += d20 * d20; acc[3] += d21 * d21;
            acc[4] += d10 * d10; acc[5] += d11 * d11;
            acc[6] += d12 * d12; acc[7] += d13 * d13;
        }
    }
#pragma unroll
    for (int off = 16; off; off >>= 1)
#pragma unroll
        for (int j = 0; j < 16; j++) acc[j] += __shfl_xor_sync(FULLM, acc[j], off);

    __shared__ float sred[8 * 16];
    int lane = tid & 31, wid = tid >> 5;
    if (lane == 0)
#pragma unroll
        for (int j = 0; j < 16; j++) sred[wid * 16 + j] = acc[j];
    __syncthreads();
    if (tid < 16) {
        float s = 0.0f;
#pragma unroll
        for (int w = 0; w < 8; w++) s += sred[w * 16 + tid];
        int base = b * Sc;
        if (tid < 8) {
            int idx;
            if (tid == 0) idx = g;
            else if (tid == 1) idx = 256 + g;
            else if (tid < 4) idx = 512 + 2 * g + (tid - 2);
            else idx = 1024 + 4 * g + (tid - 4);
            g_ssq[base + idx] = s;
        } else {
            g_pt[base + 8 * g + (tid - 8)] = s;
        }
    }
}

// ---------------- small helpers ------------------------------------------
__device__ __forceinline__ float4 ld4(const float* p) { return *(const float4*)p; }
__device__ __forceinline__ void st4(float* p, float4 v) { *(float4*)p = v; }
__device__ __forceinline__ void st4h(float* A, int i0, float4 v) {
    *(float4*)(A + i0) = v;
    if (i0 < HAL) *(float4*)(A + i0 + Sc) = v;
    if (i0 >= Sc - HAL) *(float4*)(A + i0 - Sc) = v;
}
__device__ __forceinline__ void sth(float* A, int i, float v) {
    A[i] = v;
    if (i < HAL) A[i + Sc] = v;
    if (i >= Sc - HAL) A[i - Sc] = v;
}

// ------------- single-barrier reductions (512 thr, 16 warps) -------------
__device__ __forceinline__ float bsum1(float v, float* red, int& sl) {
#pragma unroll
    for (int o = 16; o; o >>= 1) v += __shfl_xor_sync(FULLM, v, o);
    int lane = threadIdx.x & 31, wid = threadIdx.x >> 5;
    if (lane == 0) red[sl * 16 + wid] = v;
    __syncthreads();
    float s = 0.0f;
    const float* rr = red + sl * 16;
#pragma unroll
    for (int w = 0; w < 16; w++) s += rr[w];
    sl ^= 1;
    return s;
}

// dual sum in one barrier: second sum goes to red2 (16 floats)
__device__ __forceinline__ float bsum2(float v, float v2, float* red, float* red2,
                                       int& sl, float* out2) {
#pragma unroll
    for (int o = 16; o; o >>= 1) {
        v += __shfl_xor_sync(FULLM, v, o);
        v2 += __shfl_xor_sync(FULLM, v2, o);
    }
    int lane = threadIdx.x & 31, wid = threadIdx.x >> 5;
    if (lane == 0) { red[sl * 16 + wid] = v; red2[wid] = v2; }
    __syncthreads();
    float s = 0.0f, s2 = 0.0f;
    const float* rr = red + sl * 16;
#pragma unroll
    for (int w = 0; w < 16; w++) { s += rr[w]; s2 += red2[w]; }
    sl ^= 1;
    *out2 = s2;
    return s;
}

__device__ __forceinline__ float bmax1(float v, float* mred) {
#pragma unroll
    for (int o = 16; o; o >>= 1) v = fmaxf(v, __shfl_xor_sync(FULLM, v, o));
    int lane = threadIdx.x & 31, wid = threadIdx.x >> 5;
    if (lane == 0) mred[wid] = v;
    __syncthreads();
    float m = mred[0];
#pragma unroll
    for (int w = 1; w < 16; w++) m = fmaxf(m, mred[w]);
    return m;
}

// fused (max, tie-count) reduction, one barrier
__device__ __forceinline__ float bmaxcnt1(float m, float c, float* mred, float* cnt_out) {
#pragma unroll
    for (int o = 16; o; o >>= 1) {
        float m2 = __shfl_xor_sync(FULLM, m, o);
        float c2 = __shfl_xor_sync(FULLM, c, o);
        if (m2 > m) { m = m2; c = c2; }
        else if (m2 == m) { c += c2; }
    }
    int lane = threadIdx.x & 31, wid = threadIdx.x >> 5;
    if (lane == 0) { mred[wid] = m; mred[16 + wid] = c; }
    __syncthreads();
    float M = mred[0];
#pragma unroll
    for (int w = 1; w < 16; w++) M = fmaxf(M, mred[w]);
    float C = 0.0f;
#pragma unroll
    for (int w = 0; w < 16; w++) C += (mred[w] == M) ? mred[16 + w] : 0.0f;
    *cnt_out = C;
    return M;
}

// ---------------- leray: 65-tap conv (init only) -------------------------
__device__ __forceinline__ void conv_leray(float* __restrict__ dst,
                                           const float* __restrict__ src,
                                           const float* __restrict__ kl) {
    int i0 = 4 * threadIdx.x;
    const float* S = src + i0 - 32;
    float4 cur = ld4(S);
    float a0 = 0.0f, a1 = 0.0f, a2 = 0.0f, a3 = 0.0f;
#pragma unroll
    for (int m = 0; m < 17; m++) {
        float4 nxt = ld4(S + 4 * m + 4);
        float4 k4 = ld4(kl + 4 * m);
        a0 += k4.x * cur.x + k4.y * cur.y + k4.z * cur.z + k4.w * cur.w;
        a1 += k4.x * cur.y + k4.y * cur.z + k4.z * cur.w + k4.w * nxt.x;
        a2 += k4.x * cur.z + k4.y * cur.w + k4.z * nxt.x + k4.w * nxt.y;
        a3 += k4.x * cur.w + k4.y * nxt.x + k4.z * nxt.y + k4.w * nxt.z;
        cur = nxt;
    }
    st4h(dst, i0, make_float4(a0, a1, a2, a3));
    __syncthreads();
}

// ------- fused: up -= (lr/B)*leray^2(ub), 81-tap conv, no barrier --------
__device__ __forceinline__ void conv2_update(float* __restrict__ up,
                                             const float* __restrict__ ub,
                                             const float* __restrict__ kl2) {
    int i0 = 4 * threadIdx.x;
    const float* S = ub + i0 - 40;
    float4 cur = ld4(S);
    float a0 = 0.0f, a1 = 0.0f, a2 = 0.0f, a3 = 0.0f;
#pragma unroll
    for (int m = 0; m < 21; m++) {
        float4 nxt = ld4(S + 4 * m + 4);
        float4 k4 = ld4(kl2 + 4 * m);
        a0 += k4.x * cur.x + k4.y * cur.y + k4.z * cur.z + k4.w * cur.w;
        a1 += k4.x * cur.y + k4.y * cur.z + k4.z * cur.w + k4.w * nxt.x;
        a2 += k4.x * cur.z + k4.y * cur.w + k4.z * nxt.x + k4.w * nxt.y;
        a3 += k4.x * cur.w + k4.y * nxt.x + k4.z * nxt.y + k4.w * nxt.z;
        cur = nxt;
    }
    float4 u = ld4(up + i0);
    st4h(up, i0, make_float4(u.x - a0, u.y - a1, u.z - a2, u.w - a3));
}

// ---- forward advect: store RAW y, one barrier, return Z -----------------
__device__ __forceinline__ float advect_fwd(float* __restrict__ dst,
                                            const float* __restrict__ r, float iZr,
                                            const float* __restrict__ u,
                                            float dt, float* red, int& sl) {
    int i0 = 4 * threadIdx.x;
    float4 r0 = ld4(r + i0);
    float rv[6] = {r[i0 - 1] * iZr, r0.x * iZr, r0.y * iZr, r0.z * iZr, r0.w * iZr,
                   r[i0 + 4] * iZr};
    float4 u0 = ld4(u + i0);
    float uv[5] = {u[i0 - 1], u0.x, u0.y, u0.z, u0.w};
    float F[5];
#pragma unroll
    for (int k = 0; k < 5; k++)
        F[k] = uv[k] > 0.0f ? uv[k] * rv[k] : uv[k] * rv[k + 1];
    float y[4], part = 0.0f;
#pragma unroll
    for (int e = 0; e < 4; e++) {
        y[e] = fabsf(rv[e + 1] - dt * (F[e + 1] - F[e])) + 1e-8f;
        part += y[e];
    }
    st4h(dst, i0, make_float4(y[0], y[1], y[2], y[3]));
    return bsum1(part, red, sl);
}

// ---- forward advect for r4: also reduces dot((1-v), y_raw) --------------
__device__ __forceinline__ float advect_fwd_dot(float* __restrict__ dst,
                                                const float* __restrict__ r, float iZr,
                                                const float* __restrict__ u,
                                                const float* __restrict__ vA,
                                                float dt, float* red, float* red2,
                                                int& sl, float* dotraw_out) {
    int i0 = 4 * threadIdx.x;
    float4 r0 = ld4(r + i0);
    float rv[6] = {r[i0 - 1] * iZr, r0.x * iZr, r0.y * iZr, r0.z * iZr, r0.w * iZr,
                   r[i0 + 4] * iZr};
    float4 u0 = ld4(u + i0);
    float uv[5] = {u[i0 - 1], u0.x, u0.y, u0.z, u0.w};
    float F[5];
#pragma unroll
    for (int k = 0; k < 5; k++)
        F[k] = uv[k] > 0.0f ? uv[k] * rv[k] : uv[k] * rv[k + 1];
    float4 v4 = ld4(vA + i0);
    float vb[4] = {1.0f - v4.x, 1.0f - v4.y, 1.0f - v4.z, 1.0f - v4.w};
    float y[4], part = 0.0f, part2 = 0.0f;
#pragma unroll
    for (int e = 0; e < 4; e++) {
        y[e] = fabsf(rv[e + 1] - dt * (F[e + 1] - F[e])) + 1e-8f;
        part += y[e];
        part2 += vb[e] * y[e];
    }
    st4h(dst, i0, make_float4(y[0], y[1], y[2], y[3]));
    return bsum2(part, part2, red, red2, sl, dotraw_out);
}

// ---- final outer advect (with kappa), stores NORMALIZED -----------------
__device__ __forceinline__ void advect_final(float* __restrict__ dst,
                                             const float* __restrict__ r,  // normalized
                                             const float* __restrict__ u,
                                             float dt, float kap, float* red, int& sl) {
    int i0 = 4 * threadIdx.x;
    float4 r0 = ld4(r + i0);
    float rv[6] = {r[i0 - 1], r0.x, r0.y, r0.z, r0.w, r[i0 + 4]};
    float4 u0 = ld4(u + i0);
    float uv[5] = {u[i0 - 1], u0.x, u0.y, u0.z, u0.w};
    float F[5];
#pragma unroll
    for (int k = 0; k < 5; k++)
        F[k] = uv[k] > 0.0f ? uv[k] * rv[k] : uv[k] * rv[k + 1];
    float y[4], part = 0.0f;
#pragma unroll
    for (int e = 0; e < 4; e++) {
        float a = rv[e + 1] - dt * (F[e + 1] - F[e])
                + kap * dt * (rv[e + 2] + rv[e] - 2.0f * rv[e + 1]);
        y[e] = fabsf(a) + 1e-8f;
        part += y[e];
    }
    float Z = bsum1(part, red, sl);
    float iZ = 1.0f / Z;
    st4h(dst, i0, make_float4(y[0] * iZ, y[1] * iZ, y[2] * iZ, y[3] * iZ));
}

// ---- FIRST backward step: rb=(1-v) known, dot passed in; SETS ub --------
__device__ __forceinline__ float advect_bwd_first(const float* __restrict__ rt, float iZt,
                                                  float Zn, float dotraw,
                                                  const float* __restrict__ u, float dt,
                                                  const float* __restrict__ vA,
                                                  float* __restrict__ rbA,
                                                  float* __restrict__ abA,
                                                  float* __restrict__ ubA) {
    int i0 = 4 * threadIdx.x;
    float iZn = 1.0f / Zn;
    float dot = dotraw * iZn;

    float4 r0 = ld4(rt + i0);
    float rv[6] = {rt[i0 - 1] * iZt, r0.x * iZt, r0.y * iZt, r0.z * iZt, r0.w * iZt,
                   rt[i0 + 4] * iZt};
    float4 u0 = ld4(u + i0);
    float uv[5] = {u[i0 - 1], u0.x, u0.y, u0.z, u0.w};
    float F[5];
#pragma unroll
    for (int k = 0; k < 5; k++)
        F[k] = uv[k] > 0.0f ? uv[k] * rv[k] : uv[k] * rv[k + 1];

    float4 v4 = ld4(vA + i0);
    float rb[4] = {1.0f - v4.x, 1.0f - v4.y, 1.0f - v4.z, 1.0f - v4.w};
    float ab[4], dtl = 0.0f;
#pragma unroll
    for (int e = 0; e < 4; e++) {
        float a = rv[e + 1] - dt * (F[e + 1] - F[e]);
        float s = (a > 0.0f) ? 1.0f : ((a < 0.0f) ? -1.0f : 0.0f);
        ab[e] = (rb[e] - dot) * iZn * s;
        dtl -= ab[e] * (F[e + 1] - F[e]);
    }
    st4h(abA, i0, make_float4(ab[0], ab[1], ab[2], ab[3]));
    __syncthreads();

    float abv[6] = {abA[i0 - 1], ab[0], ab[1], ab[2], ab[3], abA[i0 + 4]};
    float Fb[5];
#pragma unroll
    for (int k = 0; k < 5; k++)
        Fb[k] = -dt * (abv[k] - abv[k + 1]);

    float ub[4];
#pragma unroll
    for (int e = 0; e < 4; e++)
        ub[e] = Fb[e + 1] * (uv[e + 1] > 0.0f ? rv[e + 1] : rv[e + 2]);  // SET
    st4h(ubA, i0, make_float4(ub[0], ub[1], ub[2], ub[3]));

    float nr[4];
#pragma unroll
    for (int e = 0; e < 4; e++)
        nr[e] = ab[e] + (uv[e + 1] > 0.0f ? Fb[e + 1] * uv[e + 1] : 0.0f)
                      + (uv[e] > 0.0f ? 0.0f : Fb[e] * uv[e]);
    st4(rbA + i0, make_float4(nr[0], nr[1], nr[2], nr[3]));
    return dtl;
}

// ---- middle backward steps: 2 barriers ----------------------------------
__device__ __forceinline__ float advect_bwd(const float* __restrict__ rt, float iZt,
                                            const float* __restrict__ rn, float Zn,
                                            const float* __restrict__ u, float dt,
                                            float* __restrict__ rbA,
                                            float* __restrict__ abA,
                                            float* __restrict__ ubA,
                                            float* red, int& sl) {
    int i0 = 4 * threadIdx.x;
    float4 rb4 = ld4(rbA + i0);
    float4 rn4 = ld4(rn + i0);
    float dotraw = bsum1(rb4.x * rn4.x + rb4.y * rn4.y + rb4.z * rn4.z + rb4.w * rn4.w,
                         red, sl);
    float iZn = 1.0f / Zn;
    float dot = dotraw * iZn;

    float4 r0 = ld4(rt + i0);
    float rv[6] = {rt[i0 - 1] * iZt, r0.x * iZt, r0.y * iZt, r0.z * iZt, r0.w * iZt,
                   rt[i0 + 4] * iZt};
    float4 u0 = ld4(u + i0);
    float uv[5] = {u[i0 - 1], u0.x, u0.y, u0.z, u0.w};
    float F[5];
#pragma unroll
    for (int k = 0; k < 5; k++)
        F[k] = uv[k] > 0.0f ? uv[k] * rv[k] : uv[k] * rv[k + 1];

    float rb[4] = {rb4.x, rb4.y, rb4.z, rb4.w};
    float ab[4], dtl = 0.0f;
#pragma unroll
    for (int e = 0; e < 4; e++) {
        float a = rv[e + 1] - dt * (F[e + 1] - F[e]);
        float s = (a > 0.0f) ? 1.0f : ((a < 0.0f) ? -1.0f : 0.0f);
        ab[e] = (rb[e] - dot) * iZn * s;
        dtl -= ab[e] * (F[e + 1] - F[e]);
    }
    st4h(abA, i0, make_float4(ab[0], ab[1], ab[2], ab[3]));
    __syncthreads();

    float abv[6] = {abA[i0 - 1], ab[0], ab[1], ab[2], ab[3], abA[i0 + 4]};
    float Fb[5];
#pragma unroll
    for (int k = 0; k < 5; k++)
        Fb[k] = -dt * (abv[k] - abv[k + 1]);

    float4 ub4 = ld4(ubA + i0);
    float ub[4] = {ub4.x, ub4.y, ub4.z, ub4.w};
#pragma unroll
    for (int e = 0; e < 4; e++)
        ub[e] += Fb[e + 1] * (uv[e + 1] > 0.0f ? rv[e + 1] : rv[e + 2]);
    st4h(ubA, i0, make_float4(ub[0], ub[1], ub[2], ub[3]));

    float nr[4];
#pragma unroll
    for (int e = 0; e < 4; e++)
        nr[e] = ab[e] + (uv[e + 1] > 0.0f ? Fb[e + 1] * uv[e + 1] : 0.0f)
                      + (uv[e] > 0.0f ? 0.0f : Fb[e] * uv[e]);
    st4(rbA + i0, make_float4(nr[0], nr[1], nr[2], nr[3]));
    return dtl;
}

// ---- LAST backward step: fuses dtbar reduction into its 2nd barrier -----
__device__ __forceinline__ float advect_bwd_last(const float* __restrict__ rt, float iZt,
                                                 const float* __restrict__ rn, float Zn,
                                                 const float* __restrict__ u, float dt,
                                                 float dtl_in,
                                                 float* __restrict__ rbA,
                                                 float* __restrict__ abA,
                                                 float* __restrict__ ubA,
                                                 float* red, float* red2, int& sl) {
    int i0 = 4 * threadIdx.x;
    float4 rb4 = ld4(rbA + i0);
    float4 rn4 = ld4(rn + i0);
    float dotraw = bsum1(rb4.x * rn4.x + rb4.y * rn4.y + rb4.z * rn4.z + rb4.w * rn4.w,
                         red, sl);
    float iZn = 1.0f / Zn;
    float dot = dotraw * iZn;

    float4 r0 = ld4(rt + i0);
    float rv[6] = {rt[i0 - 1] * iZt, r0.x * iZt, r0.y * iZt, r0.z * iZt, r0.w * iZt,
                   rt[i0 + 4] * iZt};
    float4 u0 = ld4(u + i0);
    float uv[5] = {u[i0 - 1], u0.x, u0.y, u0.z, u0.w};
    float F[5];
#pragma unroll
    for (int k = 0; k < 5; k++)
        F[k] = uv[k] > 0.0f ? uv[k] * rv[k] : uv[k] * rv[k + 1];

    float rb[4] = {rb4.x, rb4.y, rb4.z, rb4.w};
    float ab[4], dtl = dtl_in;
#pragma unroll
    for (int e = 0; e < 4; e++) {
        float a = rv[e + 1] - dt * (F[e + 1] - F[e]);
        float s = (a > 0.0f) ? 1.0f : ((a < 0.0f) ? -1.0f : 0.0f);
        ab[e] = (rb[e] - dot) * iZn * s;
        dtl -= ab[e] * (F[e + 1] - F[e]);
    }
    st4h(abA, i0, make_float4(ab[0], ab[1], ab[2], ab[3]));
    // fuse dtbar reduction into the abA-publish barrier
    float t = dtl;
#pragma unroll
    for (int o = 16; o; o >>= 1) t += __shfl_xor_sync(FULLM, t, o);
    int lane = threadIdx.x & 31, wid = threadIdx.x >> 5;
    if (lane == 0) red2[wid] = t;
    __syncthreads();
    float dtbar = 0.0f;
#pragma unroll
    for (int w = 0; w < 16; w++) dtbar += red2[w];

    float abv[6] = {abA[i0 - 1], ab[0], ab[1], ab[2], ab[3], abA[i0 + 4]};
    float Fb[5];
#pragma unroll
    for (int k = 0; k < 5; k++)
        Fb[k] = -dt * (abv[k] - abv[k + 1]);

    float4 ub4 = ld4(ubA + i0);
    float ub[4] = {ub4.x, ub4.y, ub4.z, ub4.w};
#pragma unroll
    for (int e = 0; e < 4; e++)
        ub[e] += Fb[e + 1] * (uv[e + 1] > 0.0f ? rv[e + 1] : rv[e + 2]);
    st4h(ubA, i0, make_float4(ub[0], ub[1], ub[2], ub[3]));
    return dtbar;
}

// ---------------- main simulation: one CTA per batch ---------------------
#define SIM_SMEM ((4416 + 11 * LD) * 4)

__global__ void __launch_bounds__(NTS, 1) sim_kernel(const float* __restrict__ phi_g) {
    extern __shared__ float sm[];
    float* klA  = sm;          // 68  (65 taps pad 68)
    float* kl2A = sm + 68;     // 84  (81 taps pad 84)
    float* red  = sm + 152;    // 32 (2 slots x 16)
    float* red2 = sm + 184;    // 16 (secondary fused sums)
    float* mred = sm + 200;    // 32 (max + cnt)
    float* phiA = sm + 232;    // 2048  (sm+232 .. sm+2280)
    float* rbA  = sm + 2280;   // 2048  (.. sm+4328; round up region to 4416)
    float* arr  = sm + 4416;   // 11 x LD haloed arrays
    float* vA   = arr + 0 * LD + HAL;
    float* up0A = arr + 1 * LD + HAL;
    float* upA  = arr + 2 * LD + HAL;
    float* rhoA = arr + 3 * LD + HAL;
    float* spA  = arr + 4 * LD + HAL;
    float* r1A  = arr + 5 * LD + HAL;
    float* r2A  = arr + 6 * LD + HAL;
    float* r3A  = arr + 7 * LD + HAL;
    float* r4A  = arr + 8 * LD + HAL;
    float* abA  = arr + 9 * LD + HAL;
    float* ubA  = arr + 10 * LD + HAL;

    int b = blockIdx.x;
    int tid = threadIdx.x;
    int i0 = 4 * tid;
    int sl = 0;

    if (tid < 68) klA[tid]  = (tid < 65) ? g_kl[tid + 19] : 0.0f;   // taps -32..32
    if (tid < 84) kl2A[tid] = (tid < 81) ? g_kl2[tid + 24] : 0.0f;  // taps -40..40
    st4(phiA + i0, ld4(phi_g + i0));

    // rho = normalize(sqrt(ssq)+eps)
    {
        float4 s4 = ld4(g_ssq + b * Sc + i0);
        float y0 = sqrtf(s4.x) + 1e-8f, y1 = sqrtf(s4.y) + 1e-8f;
        float y2 = sqrtf(s4.z) + 1e-8f, y3 = sqrtf(s4.w) + 1e-8f;
        float Z = bsum1(y0 + y1 + y2 + y3, red, sl);
        float iZ = 1.0f / Z;
        st4h(rhoA, i0, make_float4(y0 * iZ, y1 * iZ, y2 * iZ, y3 * iZ));
    }

    // v = normalize(sqrt(D)*|dwt(pt)|+eps)
    st4(r1A + i0, ld4(g_pt + b * Sc + i0));
    __syncthreads();
#pragma unroll
    for (int s = 0; s < 2; s++) {           // level 1
        int j = 2 * tid + s;
        float e = r1A[2 * j], o = r1A[2 * j + 1];
        sth(vA, 1024 + j, (e - o) * IS2);
        r2A[j] = (e + o) * IS2;
    }
    __syncthreads();
    {                                       // level 2
        float e = r2A[2 * tid], o = r2A[2 * tid + 1];
        sth(vA, 512 + tid, (e - o) * IS2);
        r1A[tid] = (e + o) * IS2;
    }
    __syncthreads();
    if (tid < 256) {                        // level 3
        float e = r1A[2 * tid], o = r1A[2 * tid + 1];
        sth(vA, 256 + tid, (e - o) * IS2);
        sth(vA, tid, (e + o) * IS2);
    }
    __syncthreads();
    {
        float4 v4 = ld4(vA + i0);
        float y0 = 45.254833995939045f * fabsf(v4.x) + 1e-8f;
        float y1 = 45.254833995939045f * fabsf(v4.y) + 1e-8f;
        float y2 = 45.254833995939045f * fabsf(v4.z) + 1e-8f;
        float y3 = 45.254833995939045f * fabsf(v4.w) + 1e-8f;
        float Z = bsum1(y0 + y1 + y2 + y3, red, sl);
        float iZ = 1.0f / Z;
        st4h(vA, i0, make_float4(y0 * iZ, y1 * iZ, y2 * iZ, y3 * iZ));
        __syncthreads();
    }

    // up0 = leray(grad1(v)) — outer-invariant
    {
        float4 v0 = ld4(vA + i0);
        float v4n = vA[i0 + 4];
        st4h(ubA, i0, make_float4(v0.y - v0.x, v0.z - v0.y, v0.w - v0.z, v4n - v0.w));
        __syncthreads();
        conv_leray(up0A, ubA, klA);
    }

    float* rho = rhoA;
    float* spare = spA;

#pragma unroll 1
    for (int k = 0; k < 3; k++) {
        float kap = (k == 0) ? 0.01f : ((k == 1) ? 0.005f : 0.0f);

        // reaction (1 mirror-descent step); stores normalized rho
        {
            float4 rh = ld4(rho + i0);
            float4 ph = ld4(phiA + i0);
            float w0 = fabsf(rh.x * expf(-0.1f * (ph.x + logf(rh.x)))) + 1e-8f;
            float w1 = fabsf(rh.y * expf(-0.1f * (ph.y + logf(rh.y)))) + 1e-8f;
            float w2 = fabsf(rh.z * expf(-0.1f * (ph.z + logf(rh.z)))) + 1e-8f;
            float w3 = fabsf(rh.w * expf(-0.1f * (ph.w + logf(rh.w)))) + 1e-8f;
            float Z = bsum1(w0 + w1 + w2 + w3, red, sl);
            float iZ = 1.0f / Z;
            st4h(rho, i0, make_float4(w0 * iZ, w1 * iZ, w2 * iZ, w3 * iZ));
        }

        // up <- up0 (full haloed range); reader offset by HAL -> must fence
        for (int q = 4 * tid; q < LD; q += 4 * NTS)
            st4(arr + 2 * LD + q, ld4(arr + 1 * LD + q));
        __syncthreads();

        // 5 inner MPC gradient steps (up = leray(u) tracked directly)
#pragma unroll 1
        for (int is = 0; is < 5; is++) {
            float4 up4 = ld4(upA + i0);
            float a0 = fabsf(up4.x), a1 = fabsf(up4.y);
            float a2 = fabsf(up4.z), a3 = fabsf(up4.w);
            float lm = fmaxf(fmaxf(a0, a1), fmaxf(a2, a3));
            float lc = (a0 == lm ? 1.0f : 0.0f) + (a1 == lm ? 1.0f : 0.0f)
                     + (a2 == lm ? 1.0f : 0.0f) + (a3 == lm ? 1.0f : 0.0f);
            float nt;
            float m = bmaxcnt1(lm, lc, mred, &nt);
            float dt = 0.4f / (m + 1e-8f);

            float z0 = advect_fwd(r1A, rho, 1.0f, upA, dt, red, sl);
            float z1 = advect_fwd(r2A, r1A, 1.0f / z0, upA, dt, red, sl);
            float z2 = advect_fwd(r3A, r2A, 1.0f / z1, upA, dt, red, sl);
            float dotraw;
            float z3 = advect_fwd_dot(r4A, r3A, 1.0f / z2, upA, vA, dt,
                                      red, red2, sl, &dotraw);

            float dtl = advect_bwd_first(r3A, 1.0f / z2, z3, dotraw, upA, dt,
                                         vA, rbA, abA, ubA);
            dtl += advect_bwd(r2A, 1.0f / z1, r3A, z2, upA, dt, rbA, abA, ubA, red, sl);
            dtl += advect_bwd(r1A, 1.0f / z0, r2A, z1, upA, dt, rbA, abA, ubA, red, sl);
            float dtbar = advect_bwd_last(rho, 1.0f, r1A, z0, upA, dt, dtl,
                                          rbA, abA, ubA, red, red2, sl);

            float mbar = dtbar * (-dt * dt * 2.5f);  // d(dt)/dm = -dt^2/CFL
            {
                float4 ub4 = ld4(ubA + i0);
                float inv_nt = mbar / nt;
                float add0 = (a0 == m) ? inv_nt * ((up4.x > 0.0f) ? 1.0f : -1.0f) : 0.0f;
                float add1 = (a1 == m) ? inv_nt * ((up4.y > 0.0f) ? 1.0f : -1.0f) : 0.0f;
                float add2 = (a2 == m) ? inv_nt * ((up4.z > 0.0f) ? 1.0f : -1.0f) : 0.0f;
                float add3 = (a3 == m) ? inv_nt * ((up4.w > 0.0f) ? 1.0f : -1.0f) : 0.0f;
                st4h(ubA, i0, make_float4(ub4.x + add0, ub4.y + add1,
                                          ub4.z + add2, ub4.w + add3));
            }
            __syncthreads();                    // publish ub before conv reads

            conv2_update(upA, ubA, kl2A);       // up -= (lr/B)*leray^2(ub)
        }

        // main advect with kappa; up already = leray(u_final)
        {
            float4 up4 = ld4(upA + i0);
            float lm = fmaxf(fmaxf(fabsf(up4.x), fabsf(up4.y)),
                             fmaxf(fabsf(up4.z), fabsf(up4.w)));
            float mm = bmax1(lm, mred);
            float dt = 0.4f / (mm + 1e-8f);
            advect_final(spare, rho, upA, dt, kap, red, sl);
            float* tmp = rho; rho = spare; spare = tmp;
        }
    }

    // rho_f = (rho + 0.1 v) / sum
    {
        float4 rh = ld4(rho + i0);
        float4 v4 = ld4(vA + i0);
        float f0 = rh.x + 0.1f * v4.x, f1 = rh.y + 0.1f * v4.y;
        float f2 = rh.z + 0.1f * v4.z, f3 = rh.w + 0.1f * v4.w;
        float Z = bsum1(f0 + f1 + f2 + f3, red, sl);
        float iZ = 1.0f / Z;
        st4(g_rhof + b * Sc + i0, make_float4(f0 * iZ, f1 * iZ, f2 * iZ, f3 * iZ));
    }
}

// ---------------- epilogue: fused inverse DWT ----------------------------
__global__ void __launch_bounds__(256) out_kernel(const float* __restrict__ bw,
                                                  float* __restrict__ out) {
    int g = blockIdx.x, b = blockIdx.y, tid = threadIdx.x;
    const float* rf = g_rhof + b * Sc;
    float rfA = rf[g];
    float rf3 = rf[256 + g];
    float rf2a = rf[512 + 2 * g], rf2b = rf[512 + 2 * g + 1];
    float rf1_0 = rf[1024 + 4 * g], rf1_1 = rf[1024 + 4 * g + 1];
    float rf1_2 = rf[1024 + 4 * g + 2], rf1_3 = rf[1024 + 4 * g + 3];

    const float C8 = 0.35355339059327376220f;  // 1/(2*sqrt(2))
    float cA = rfA * C8;
    float c3 = rf3 * C8;
    float c2arr[2] = {rf2a * 0.5f, rf2b * 0.5f};
    float c1arr[4] = {rf1_0 * IS2, rf1_1 * IS2, rf1_2 * IS2, rf1_3 * IS2};

    const float4* bw4 = (const float4*)bw;
    float4* o4 = (float4*)(out + ((size_t)b * Sc + 8 * (size_t)g) * Dc);
#pragma unroll
    for (int c = 0; c < 2; c++) {
        int c4 = tid + c * 256;
        float4 b0 = bw4[0 * 512 + c4];
        float4 b1 = bw4[1 * 512 + c4];
        float4 b2 = bw4[2 * 512 + c4];
        float4 b3 = bw4[3 * 512 + c4];
#pragma unroll
        for (int r = 0; r < 8; r++) {
            float s2 = (r < 4) ? 1.0f : -1.0f;
            float s1 = (((r >> 1) & 1) == 0) ? 1.0f : -1.0f;
            float s0 = ((r & 1) == 0) ? 1.0f : -1.0f;
            float k0 = cA;
            float k1 = s2 * c3;
            float k2 = s1 * c2arr[r >> 2];
            float k3 = s0 * c1arr[r >> 1];
            float4 o;
            o.x = k0 * b0.x + k1 * b1.x + k2 * b2.x + k3 * b3.x;
            o.y = k0 * b0.y + k1 * b1.y + k2 * b2.y + k3 * b3.y;
            o.z = k0 * b0.z + k1 * b1.z + k2 * b2.z + k3 * b3.z;
            o.w = k0 * b0.w + k1 * b1.w + k2 * b2.w + k3 * b3.w;
            o4[r * 512 + c4] = o;
        }
    }
}

// ---------------- launch --------------------------------------------------
extern "C" void kernel_launch(void* const* d_in, const int* in_sizes, int n_in,
                              void* d_out, int out_size) {
    const float* x    = (const float*)d_in[0];
    const float* wval = (const float*)d_in[1];
    const float* phi  = (const float*)d_in[2];
    const float* bw   = (const float*)d_in[3];
    float* out = (float*)d_out;

    cudaFuncSetAttribute(sim_kernel, cudaFuncAttributeMaxDynamicSharedMemorySize, SIM_SMEM);

    setup_kl_kernel<<<1, 256>>>();
    prep_kernel<<<dim3(256, 8), 256>>>(x, wval);
    sim_kernel<<<8, NTS, SIM_SMEM>>>(phi);
    out_kernel<<<dim3(256, 8), 256>>>(bw, out);
}

// round 11
// speedup vs baseline: 2.1648x; 1.0660x over previous
#include <cuda_runtime.h>
#include <math.h>

#define Sc 2048
#define Dc 2048
#define NTS 512
#define FULLM 0xffffffffu
#define IS2 0.70710678118654752440f
#define HAL 72
#define LD 2192

// ---------------- device scratch ----------------------------------------
__device__ float g_ssq[8 * Sc];   // sum over d of dwt coeff^2
__device__ float g_pt[8 * Sc];    // per-token dot with w_val
__device__ float g_rhof[8 * Sc];  // final rho_f (normalized)

// ---------------- compile-time leray taps --------------------------------
// leray = I - grad1(Jacobi50(div1(.))) : fixed circulant, independent of all
// inputs. Computed in double at COMPILE time so conv multipliers become
// float immediates (FFMA-imm has rt_SMSP=1, 2x the 3-reg form).
// NOTE: accessed via a local `constexpr Taps` inside each device function —
// a namespace-scope constexpr variable needs --expt-relaxed-constexpr, which
// the harness does not pass. The function is __host__ __device__ so the
// constexpr local is legal device code and folds at compile time.
struct Taps {
    float k[68];    // leray taps, disp -32..+32 (65 used, pad 68)
    float k2[84];   // 0.0125 * (kl conv kl), disp -40..+40 (81 used, pad 84)
};
__host__ __device__ constexpr Taps make_taps() {
    Taps t = {};
    double p[256] = {};
    double pn[256] = {};
    for (int it = 0; it < 50; it++) {
        for (int i = 0; i < 256; i++) {
            double l = (i > 0) ? p[i - 1] : 0.0;
            double r = (i < 255) ? p[i + 1] : 0.0;
            double bb = (i == 128) ? 1.0 : ((i == 129) ? -1.0 : 0.0);
            pn[i] = 0.5 * (r + l - bb);
        }
        for (int i = 0; i < 256; i++) p[i] = pn[i];
    }
    double kl[103] = {};
    for (int j = 0; j < 103; j++) {
        int i = 77 + j;                      // disp = j - 51
        double del = (i == 128) ? 1.0 : 0.0;
        kl[j] = del - (p[i + 1] - p[i]);
    }
    for (int j = 0; j < 68; j++)
        t.k[j] = (j < 65) ? (float)kl[j + 19] : 0.0f;
    for (int j = 0; j < 84; j++) {
        double s = 0.0;
        if (j < 81) {
            int d = j - 40;
            for (int a = -51; a <= 51; a++) {
                int e = d - a;
                if (e >= -51 && e <= 51) s += kl[a + 51] * kl[e + 51];
            }
            s *= 0.0125;                     // INNER_LR / B folded in
        }
        t.k2[j] = (float)s;
    }
    return t;
}

// ---------------- prep: DWT energies + per-token dots --------------------
__global__ void __launch_bounds__(256) prep_kernel(const float* __restrict__ x,
                                                   const float* __restrict__ wval) {
    int g = blockIdx.x;   // 0..255
    int b = blockIdx.y;   // 0..7
    int tid = threadIdx.x;
    const float4* xv = (const float4*)(x + ((size_t)b * Sc + 8 * (size_t)g) * Dc);
    const float4* wv = (const float4*)wval;

    float acc[16];
#pragma unroll
    for (int i = 0; i < 16; i++) acc[i] = 0.0f;

#pragma unroll
    for (int c = 0; c < 2; c++) {
        int c4 = tid + c * 256;
        float4 w4 = wv[c4];
        float xr[4][8];
#pragma unroll
        for (int r = 0; r < 8; r++) {
            float4 q = xv[r * 512 + c4];
            xr[0][r] = q.x; xr[1][r] = q.y; xr[2][r] = q.z; xr[3][r] = q.w;
        }
        float wc[4] = {w4.x, w4.y, w4.z, w4.w};
#pragma unroll
        for (int cc = 0; cc < 4; cc++) {
            const float* X = xr[cc];
            float w = wc[cc];
#pragma unroll
            for (int r = 0; r < 8; r++) acc[8 + r] += X[r] * w;
            float a10 = (X[0] + X[1]) * IS2, d10 = (X[0] - X[1]) * IS2;
            float a11 = (X[2] + X[3]) * IS2, d11 = (X[2] - X[3]) * IS2;
            float a12 = (X[4] + X[5]) * IS2, d12 = (X[4] - X[5]) * IS2;
            float a13 = (X[6] + X[7]) * IS2, d13 = (X[6] - X[7]) * IS2;
            float a20 = (a10 + a11) * IS2, d20 = (a10 - a11) * IS2;
            float a21 = (a12 + a13) * IS2, d21 = (a12 - a13) * IS2;
            float a3 = (a20 + a21) * IS2, d3 = (a20 - a21) * IS2;
            acc[0] += a3 * a3;   acc[1] += d3 * d3;
            acc[2] += d20 * d20; acc[3] += d21 * d21;
            acc[4] += d10 * d10; acc[5] += d11 * d11;
            acc[6] += d12 * d12; acc[7] += d13 * d13;
        }
    }
#pragma unroll
    for (int off = 16; off; off >>= 1)
#pragma unroll
        for (int j = 0; j < 16; j++) acc[j] += __shfl_xor_sync(FULLM, acc[j], off);

    __shared__ float sred[8 * 16];
    int lane = tid & 31, wid = tid >> 5;
    if (lane == 0)
#pragma unroll
        for (int j = 0; j < 16; j++) sred[wid * 16 + j] = acc[j];
    __syncthreads();
    if (tid < 16) {
        float s = 0.0f;
#pragma unroll
        for (int w = 0; w < 8; w++) s += sred[w * 16 + tid];
        int base = b * Sc;
        if (tid < 8) {
            int idx;
            if (tid == 0) idx = g;
            else if (tid == 1) idx = 256 + g;
            else if (tid < 4) idx = 512 + 2 * g + (tid - 2);
            else idx = 1024 + 4 * g + (tid - 4);
            g_ssq[base + idx] = s;
        } else {
            g_pt[base + 8 * g + (tid - 8)] = s;
        }
    }
}

// ---------------- small helpers ------------------------------------------
__device__ __forceinline__ float4 ld4(const float* p) { return *(const float4*)p; }
__device__ __forceinline__ void st4(float* p, float4 v) { *(float4*)p = v; }
__device__ __forceinline__ void st4h(float* A, int i0, float4 v) {
    *(float4*)(A + i0) = v;
    if (i0 < HAL) *(float4*)(A + i0 + Sc) = v;
    if (i0 >= Sc - HAL) *(float4*)(A + i0 - Sc) = v;
}
__device__ __forceinline__ void sth(float* A, int i, float v) {
    A[i] = v;
    if (i < HAL) A[i + Sc] = v;
    if (i >= Sc - HAL) A[i - Sc] = v;
}

// ------------- single-barrier reductions (512 thr, 16 warps) -------------
__device__ __forceinline__ float bsum1(float v, float* red, int& sl) {
#pragma unroll
    for (int o = 16; o; o >>= 1) v += __shfl_xor_sync(FULLM, v, o);
    int lane = threadIdx.x & 31, wid = threadIdx.x >> 5;
    if (lane == 0) red[sl * 16 + wid] = v;
    __syncthreads();
    float s = 0.0f;
    const float* rr = red + sl * 16;
#pragma unroll
    for (int w = 0; w < 16; w++) s += rr[w];
    sl ^= 1;
    return s;
}

// dual sum in one barrier: second sum goes to red2 (16 floats)
__device__ __forceinline__ float bsum2(float v, float v2, float* red, float* red2,
                                       int& sl, float* out2) {
#pragma unroll
    for (int o = 16; o; o >>= 1) {
        v += __shfl_xor_sync(FULLM, v, o);
        v2 += __shfl_xor_sync(FULLM, v2, o);
    }
    int lane = threadIdx.x & 31, wid = threadIdx.x >> 5;
    if (lane == 0) { red[sl * 16 + wid] = v; red2[wid] = v2; }
    __syncthreads();
    float s = 0.0f, s2 = 0.0f;
    const float* rr = red + sl * 16;
#pragma unroll
    for (int w = 0; w < 16; w++) { s += rr[w]; s2 += red2[w]; }
    sl ^= 1;
    *out2 = s2;
    return s;
}

__device__ __forceinline__ float bmax1(float v, float* mred) {
#pragma unroll
    for (int o = 16; o; o >>= 1) v = fmaxf(v, __shfl_xor_sync(FULLM, v, o));
    int lane = threadIdx.x & 31, wid = threadIdx.x >> 5;
    if (lane == 0) mred[wid] = v;
    __syncthreads();
    float m = mred[0];
#pragma unroll
    for (int w = 1; w < 16; w++) m = fmaxf(m, mred[w]);
    return m;
}

// fused (max, tie-count) reduction, one barrier
__device__ __forceinline__ float bmaxcnt1(float m, float c, float* mred, float* cnt_out) {
#pragma unroll
    for (int o = 16; o; o >>= 1) {
        float m2 = __shfl_xor_sync(FULLM, m, o);
        float c2 = __shfl_xor_sync(FULLM, c, o);
        if (m2 > m) { m = m2; c = c2; }
        else if (m2 == m) { c += c2; }
    }
    int lane = threadIdx.x & 31, wid = threadIdx.x >> 5;
    if (lane == 0) { mred[wid] = m; mred[16 + wid] = c; }
    __syncthreads();
    float M = mred[0];
#pragma unroll
    for (int w = 1; w < 16; w++) M = fmaxf(M, mred[w]);
    float C = 0.0f;
#pragma unroll
    for (int w = 0; w < 16; w++) C += (mred[w] == M) ? mred[16 + w] : 0.0f;
    *cnt_out = C;
    return M;
}

// ---------------- leray: 65-tap conv, immediate taps (init only) ---------
__device__ __forceinline__ void conv_leray(float* __restrict__ dst,
                                           const float* __restrict__ src) {
    constexpr Taps TAPS = make_taps();   // compile-time; folds to immediates
    int i0 = 4 * threadIdx.x;
    const float* S = src + i0 - 32;
    float4 cur = ld4(S);
    float a0 = 0.0f, a1 = 0.0f, a2 = 0.0f, a3 = 0.0f;
#pragma unroll
    for (int m = 0; m < 17; m++) {
        float4 nxt = ld4(S + 4 * m + 4);
        const float kx = TAPS.k[4 * m], ky = TAPS.k[4 * m + 1];
        const float kz = TAPS.k[4 * m + 2], kw = TAPS.k[4 * m + 3];
        a0 += kx * cur.x + ky * cur.y + kz * cur.z + kw * cur.w;
        a1 += kx * cur.y + ky * cur.z + kz * cur.w + kw * nxt.x;
        a2 += kx * cur.z + ky * cur.w + kz * nxt.x + kw * nxt.y;
        a3 += kx * cur.w + ky * nxt.x + kz * nxt.y + kw * nxt.z;
        cur = nxt;
    }
    st4h(dst, i0, make_float4(a0, a1, a2, a3));
    __syncthreads();
}

// ------- fused: up -= (lr/B)*leray^2(ub), 81-tap imm conv, no barrier ----
__device__ __forceinline__ void conv2_update(float* __restrict__ up,
                                             const float* __restrict__ ub) {
    constexpr Taps TAPS = make_taps();   // compile-time; folds to immediates
    int i0 = 4 * threadIdx.x;
    const float* S = ub + i0 - 40;
    float4 cur = ld4(S);
    float a0 = 0.0f, a1 = 0.0f, a2 = 0.0f, a3 = 0.0f;
#pragma unroll
    for (int m = 0; m < 21; m++) {
        float4 nxt = ld4(S + 4 * m + 4);
        const float kx = TAPS.k2[4 * m], ky = TAPS.k2[4 * m + 1];
        const float kz = TAPS.k2[4 * m + 2], kw = TAPS.k2[4 * m + 3];
        a0 += kx * cur.x + ky * cur.y + kz * cur.z + kw * cur.w;
        a1 += kx * cur.y + ky * cur.z + kz * cur.w + kw * nxt.x;
        a2 += kx * cur.z + ky * cur.w + kz * nxt.x + kw * nxt.y;
        a3 += kx * cur.w + ky * nxt.x + kz * nxt.y + kw * nxt.z;
        cur = nxt;
    }
    float4 u = ld4(up + i0);
    st4h(up, i0, make_float4(u.x - a0, u.y - a1, u.z - a2, u.w - a3));
}

// ---- forward advect: store RAW y, one barrier, return Z -----------------
__device__ __forceinline__ float advect_fwd(float* __restrict__ dst,
                                            const float* __restrict__ r, float iZr,
                                            const float* __restrict__ u,
                                            float dt, float* red, int& sl) {
    int i0 = 4 * threadIdx.x;
    float4 r0 = ld4(r + i0);
    float rv[6] = {r[i0 - 1] * iZr, r0.x * iZr, r0.y * iZr, r0.z * iZr, r0.w * iZr,
                   r[i0 + 4] * iZr};
    float4 u0 = ld4(u + i0);
    float uv[5] = {u[i0 - 1], u0.x, u0.y, u0.z, u0.w};
    float F[5];
#pragma unroll
    for (int k = 0; k < 5; k++)
        F[k] = uv[k] > 0.0f ? uv[k] * rv[k] : uv[k] * rv[k + 1];
    float y[4], part = 0.0f;
#pragma unroll
    for (int e = 0; e < 4; e++) {
        y[e] = fabsf(rv[e + 1] - dt * (F[e + 1] - F[e])) + 1e-8f;
        part += y[e];
    }
    st4h(dst, i0, make_float4(y[0], y[1], y[2], y[3]));
    return bsum1(part, red, sl);
}

// ---- forward advect for r4: also reduces dot((1-v), y_raw) --------------
__device__ __forceinline__ float advect_fwd_dot(float* __restrict__ dst,
                                                const float* __restrict__ r, float iZr,
                                                const float* __restrict__ u,
                                                const float* __restrict__ vA,
                                                float dt, float* red, float* red2,
                                                int& sl, float* dotraw_out) {
    int i0 = 4 * threadIdx.x;
    float4 r0 = ld4(r + i0);
    float rv[6] = {r[i0 - 1] * iZr, r0.x * iZr, r0.y * iZr, r0.z * iZr, r0.w * iZr,
                   r[i0 + 4] * iZr};
    float4 u0 = ld4(u + i0);
    float uv[5] = {u[i0 - 1], u0.x, u0.y, u0.z, u0.w};
    float F[5];
#pragma unroll
    for (int k = 0; k < 5; k++)
        F[k] = uv[k] > 0.0f ? uv[k] * rv[k] : uv[k] * rv[k + 1];
    float4 v4 = ld4(vA + i0);
    float vb[4] = {1.0f - v4.x, 1.0f - v4.y, 1.0f - v4.z, 1.0f - v4.w};
    float y[4], part = 0.0f, part2 = 0.0f;
#pragma unroll
    for (int e = 0; e < 4; e++) {
        y[e] = fabsf(rv[e + 1] - dt * (F[e + 1] - F[e])) + 1e-8f;
        part += y[e];
        part2 += vb[e] * y[e];
    }
    st4h(dst, i0, make_float4(y[0], y[1], y[2], y[3]));
    return bsum2(part, part2, red, red2, sl, dotraw_out);
}

// ---- final outer advect (with kappa), stores NORMALIZED -----------------
__device__ __forceinline__ void advect_final(float* __restrict__ dst,
                                             const float* __restrict__ r,  // normalized
                                             const float* __restrict__ u,
                                             float dt, float kap, float* red, int& sl) {
    int i0 = 4 * threadIdx.x;
    float4 r0 = ld4(r + i0);
    float rv[6] = {r[i0 - 1], r0.x, r0.y, r0.z, r0.w, r[i0 + 4]};
    float4 u0 = ld4(u + i0);
    float uv[5] = {u[i0 - 1], u0.x, u0.y, u0.z, u0.w};
    float F[5];
#pragma unroll
    for (int k = 0; k < 5; k++)
        F[k] = uv[k] > 0.0f ? uv[k] * rv[k] : uv[k] * rv[k + 1];
    float y[4], part = 0.0f;
#pragma unroll
    for (int e = 0; e < 4; e++) {
        float a = rv[e + 1] - dt * (F[e + 1] - F[e])
                + kap * dt * (rv[e + 2] + rv[e] - 2.0f * rv[e + 1]);
        y[e] = fabsf(a) + 1e-8f;
        part += y[e];
    }
    float Z = bsum1(part, red, sl);
    float iZ = 1.0f / Z;
    st4h(dst, i0, make_float4(y[0] * iZ, y[1] * iZ, y[2] * iZ, y[3] * iZ));
}

// ---- FIRST backward step: rb=(1-v) known, dot passed in; SETS ub --------
__device__ __forceinline__ float advect_bwd_first(const float* __restrict__ rt, float iZt,
                                                  float Zn, float dotraw,
                                                  const float* __restrict__ u, float dt,
                                                  const float* __restrict__ vA,
                                                  float* __restrict__ rbA,
                                                  float* __restrict__ abA,
                                                  float* __restrict__ ubA) {
    int i0 = 4 * threadIdx.x;
    float iZn = 1.0f / Zn;
    float dot = dotraw * iZn;

    float4 r0 = ld4(rt + i0);
    float rv[6] = {rt[i0 - 1] * iZt, r0.x * iZt, r0.y * iZt, r0.z * iZt, r0.w * iZt,
                   rt[i0 + 4] * iZt};
    float4 u0 = ld4(u + i0);
    float uv[5] = {u[i0 - 1], u0.x, u0.y, u0.z, u0.w};
    float F[5];
#pragma unroll
    for (int k = 0; k < 5; k++)
        F[k] = uv[k] > 0.0f ? uv[k] * rv[k] : uv[k] * rv[k + 1];

    float4 v4 = ld4(vA + i0);
    float rb[4] = {1.0f - v4.x, 1.0f - v4.y, 1.0f - v4.z, 1.0f - v4.w};
    float ab[4], dtl = 0.0f;
#pragma unroll
    for (int e = 0; e < 4; e++) {
        float a = rv[e + 1] - dt * (F[e + 1] - F[e]);
        float s = (a > 0.0f) ? 1.0f : ((a < 0.0f) ? -1.0f : 0.0f);
        ab[e] = (rb[e] - dot) * iZn * s;
        dtl -= ab[e] * (F[e + 1] - F[e]);
    }
    st4h(abA, i0, make_float4(ab[0], ab[1], ab[2], ab[3]));
    __syncthreads();

    float abv[6] = {abA[i0 - 1], ab[0], ab[1], ab[2], ab[3], abA[i0 + 4]};
    float Fb[5];
#pragma unroll
    for (int k = 0; k < 5; k++)
        Fb[k] = -dt * (abv[k] - abv[k + 1]);

    float ub[4];
#pragma unroll
    for (int e = 0; e < 4; e++)
        ub[e] = Fb[e + 1] * (uv[e + 1] > 0.0f ? rv[e + 1] : rv[e + 2]);  // SET
    st4h(ubA, i0, make_float4(ub[0], ub[1], ub[2], ub[3]));

    float nr[4];
#pragma unroll
    for (int e = 0; e < 4; e++)
        nr[e] = ab[e] + (uv[e + 1] > 0.0f ? Fb[e + 1] * uv[e + 1] : 0.0f)
                      + (uv[e] > 0.0f ? 0.0f : Fb[e] * uv[e]);
    st4(rbA + i0, make_float4(nr[0], nr[1], nr[2], nr[3]));
    return dtl;
}

// ---- middle backward steps: 2 barriers ----------------------------------
__device__ __forceinline__ float advect_bwd(const float* __restrict__ rt, float iZt,
                                            const float* __restrict__ rn, float Zn,
                                            const float* __restrict__ u, float dt,
                                            float* __restrict__ rbA,
                                            float* __restrict__ abA,
                                            float* __restrict__ ubA,
                                            float* red, int& sl) {
    int i0 = 4 * threadIdx.x;
    float4 rb4 = ld4(rbA + i0);
    float4 rn4 = ld4(rn + i0);
    float dotraw = bsum1(rb4.x * rn4.x + rb4.y * rn4.y + rb4.z * rn4.z + rb4.w * rn4.w,
                         red, sl);
    float iZn = 1.0f / Zn;
    float dot = dotraw * iZn;

    float4 r0 = ld4(rt + i0);
    float rv[6] = {rt[i0 - 1] * iZt, r0.x * iZt, r0.y * iZt, r0.z * iZt, r0.w * iZt,
                   rt[i0 + 4] * iZt};
    float4 u0 = ld4(u + i0);
    float uv[5] = {u[i0 - 1], u0.x, u0.y, u0.z, u0.w};
    float F[5];
#pragma unroll
    for (int k = 0; k < 5; k++)
        F[k] = uv[k] > 0.0f ? uv[k] * rv[k] : uv[k] * rv[k + 1];

    float rb[4] = {rb4.x, rb4.y, rb4.z, rb4.w};
    float ab[4], dtl = 0.0f;
#pragma unroll
    for (int e = 0; e < 4; e++) {
        float a = rv[e + 1] - dt * (F[e + 1] - F[e]);
        float s = (a > 0.0f) ? 1.0f : ((a < 0.0f) ? -1.0f : 0.0f);
        ab[e] = (rb[e] - dot) * iZn * s;
        dtl -= ab[e] * (F[e + 1] - F[e]);
    }
    st4h(abA, i0, make_float4(ab[0], ab[1], ab[2], ab[3]));
    __syncthreads();

    float abv[6] = {abA[i0 - 1], ab[0], ab[1], ab[2], ab[3], abA[i0 + 4]};
    float Fb[5];
#pragma unroll
    for (int k = 0; k < 5; k++)
        Fb[k] = -dt * (abv[k] - abv[k + 1]);

    float4 ub4 = ld4(ubA + i0);
    float ub[4] = {ub4.x, ub4.y, ub4.z, ub4.w};
#pragma unroll
    for (int e = 0; e < 4; e++)
        ub[e] += Fb[e + 1] * (uv[e + 1] > 0.0f ? rv[e + 1] : rv[e + 2]);
    st4h(ubA, i0, make_float4(ub[0], ub[1], ub[2], ub[3]));

    float nr[4];
#pragma unroll
    for (int e = 0; e < 4; e++)
        nr[e] = ab[e] + (uv[e + 1] > 0.0f ? Fb[e + 1] * uv[e + 1] : 0.0f)
                      + (uv[e] > 0.0f ? 0.0f : Fb[e] * uv[e]);
    st4(rbA + i0, make_float4(nr[0], nr[1], nr[2], nr[3]));
    return dtl;
}

// ---- LAST backward step: fuses dtbar reduction into its 2nd barrier -----
__device__ __forceinline__ float advect_bwd_last(const float* __restrict__ rt, float iZt,
                                                 const float* __restrict__ rn, float Zn,
                                                 const float* __restrict__ u, float dt,
                                                 float dtl_in,
                                                 float* __restrict__ rbA,
                                                 float* __restrict__ abA,
                                                 float* __restrict__ ubA,
                                                 float* red, float* red2, int& sl) {
    int i0 = 4 * threadIdx.x;
    float4 rb4 = ld4(rbA + i0);
    float4 rn4 = ld4(rn + i0);
    float dotraw = bsum1(rb4.x * rn4.x + rb4.y * rn4.y + rb4.z * rn4.z + rb4.w * rn4.w,
                         red, sl);
    float iZn = 1.0f / Zn;
    float dot = dotraw * iZn;

    float4 r0 = ld4(rt + i0);
    float rv[6] = {rt[i0 - 1] * iZt, r0.x * iZt, r0.y * iZt, r0.z * iZt, r0.w * iZt,
                   rt[i0 + 4] * iZt};
    float4 u0 = ld4(u + i0);
    float uv[5] = {u[i0 - 1], u0.x, u0.y, u0.z, u0.w};
    float F[5];
#pragma unroll
    for (int k = 0; k < 5; k++)
        F[k] = uv[k] > 0.0f ? uv[k] * rv[k] : uv[k] * rv[k + 1];

    float rb[4] = {rb4.x, rb4.y, rb4.z, rb4.w};
    float ab[4], dtl = dtl_in;
#pragma unroll
    for (int e = 0; e < 4; e++) {
        float a = rv[e + 1] - dt * (F[e + 1] - F[e]);
        float s = (a > 0.0f) ? 1.0f : ((a < 0.0f) ? -1.0f : 0.0f);
        ab[e] = (rb[e] - dot) * iZn * s;
        dtl -= ab[e] * (F[e + 1] - F[e]);
    }
    st4h(abA, i0, make_float4(ab[0], ab[1], ab[2], ab[3]));
    // fuse dtbar reduction into the abA-publish barrier
    float t = dtl;
#pragma unroll
    for (int o = 16; o; o >>= 1) t += __shfl_xor_sync(FULLM, t, o);
    int lane = threadIdx.x & 31, wid = threadIdx.x >> 5;
    if (lane == 0) red2[wid] = t;
    __syncthreads();
    float dtbar = 0.0f;
#pragma unroll
    for (int w = 0; w < 16; w++) dtbar += red2[w];

    float abv[6] = {abA[i0 - 1], ab[0], ab[1], ab[2], ab[3], abA[i0 + 4]};
    float Fb[5];
#pragma unroll
    for (int k = 0; k < 5; k++)
        Fb[k] = -dt * (abv[k] - abv[k + 1]);

    float4 ub4 = ld4(ubA + i0);
    float ub[4] = {ub4.x, ub4.y, ub4.z, ub4.w};
#pragma unroll
    for (int e = 0; e < 4; e++)
        ub[e] += Fb[e + 1] * (uv[e + 1] > 0.0f ? rv[e + 1] : rv[e + 2]);
    st4h(ubA, i0, make_float4(ub[0], ub[1], ub[2], ub[3]));
    return dtbar;
}

// ---------------- main simulation: one CTA per batch ---------------------
#define SIM_SMEM ((4176 + 11 * LD) * 4)

__global__ void __launch_bounds__(NTS, 1) sim_kernel(const float* __restrict__ phi_g) {
    extern __shared__ float sm[];
    float* red  = sm;          // 32 (2 slots x 16)
    float* red2 = sm + 32;     // 16 (secondary fused sums)
    float* mred = sm + 48;     // 32 (max + cnt)
    float* phiA = sm + 80;     // 2048
    float* rbA  = sm + 2128;   // 2048
    float* arr  = sm + 4176;   // 11 x LD haloed arrays
    float* vA   = arr + 0 * LD + HAL;
    float* up0A = arr + 1 * LD + HAL;
    float* upA  = arr + 2 * LD + HAL;
    float* rhoA = arr + 3 * LD + HAL;
    float* spA  = arr + 4 * LD + HAL;
    float* r1A  = arr + 5 * LD + HAL;
    float* r2A  = arr + 6 * LD + HAL;
    float* r3A  = arr + 7 * LD + HAL;
    float* r4A  = arr + 8 * LD + HAL;
    float* abA  = arr + 9 * LD + HAL;
    float* ubA  = arr + 10 * LD + HAL;

    int b = blockIdx.x;
    int tid = threadIdx.x;
    int i0 = 4 * tid;
    int sl = 0;

    st4(phiA + i0, ld4(phi_g + i0));

    // rho = normalize(sqrt(ssq)+eps)
    {
        float4 s4 = ld4(g_ssq + b * Sc + i0);
        float y0 = sqrtf(s4.x) + 1e-8f, y1 = sqrtf(s4.y) + 1e-8f;
        float y2 = sqrtf(s4.z) + 1e-8f, y3 = sqrtf(s4.w) + 1e-8f;
        float Z = bsum1(y0 + y1 + y2 + y3, red, sl);
        float iZ = 1.0f / Z;
        st4h(rhoA, i0, make_float4(y0 * iZ, y1 * iZ, y2 * iZ, y3 * iZ));
    }

    // v = normalize(sqrt(D)*|dwt(pt)|+eps)
    st4(r1A + i0, ld4(g_pt + b * Sc + i0));
    __syncthreads();
#pragma unroll
    for (int s = 0; s < 2; s++) {           // level 1
        int j = 2 * tid + s;
        float e = r1A[2 * j], o = r1A[2 * j + 1];
        sth(vA, 1024 + j, (e - o) * IS2);
        r2A[j] = (e + o) * IS2;
    }
    __syncthreads();
    {                                       // level 2
        float e = r2A[2 * tid], o = r2A[2 * tid + 1];
        sth(vA, 512 + tid, (e - o) * IS2);
        r1A[tid] = (e + o) * IS2;
    }
    __syncthreads();
    if (tid < 256) {                        // level 3
        float e = r1A[2 * tid], o = r1A[2 * tid + 1];
        sth(vA, 256 + tid, (e - o) * IS2);
        sth(vA, tid, (e + o) * IS2);
    }
    __syncthreads();
    {
        float4 v4 = ld4(vA + i0);
        float y0 = 45.254833995939045f * fabsf(v4.x) + 1e-8f;
        float y1 = 45.254833995939045f * fabsf(v4.y) + 1e-8f;
        float y2 = 45.254833995939045f * fabsf(v4.z) + 1e-8f;
        float y3 = 45.254833995939045f * fabsf(v4.w) + 1e-8f;
        float Z = bsum1(y0 + y1 + y2 + y3, red, sl);
        float iZ = 1.0f / Z;
        st4h(vA, i0, make_float4(y0 * iZ, y1 * iZ, y2 * iZ, y3 * iZ));
        __syncthreads();
    }

    // up0 = leray(grad1(v)) — outer-invariant
    {
        float4 v0 = ld4(vA + i0);
        float v4n = vA[i0 + 4];
        st4h(ubA, i0, make_float4(v0.y - v0.x, v0.z - v0.y, v0.w - v0.z, v4n - v0.w));
        __syncthreads();
        conv_leray(up0A, ubA);
    }

    float* rho = rhoA;
    float* spare = spA;

#pragma unroll 1
    for (int k = 0; k < 3; k++) {
        float kap = (k == 0) ? 0.01f : ((k == 1) ? 0.005f : 0.0f);

        // up <- up0 copy (raw-aligned). The reaction's bsum1 barrier below
        // orders these stores before the inner loop's halo-shifted reads.
        // WAW vs last outer's conv2 writes is ordered by bmax1/advect_final.
        for (int q = 4 * tid; q < LD; q += 4 * NTS)
            st4(arr + 2 * LD + q, ld4(arr + 1 * LD + q));

        // reaction (1 mirror-descent step); stores normalized rho
        {
            float4 rh = ld4(rho + i0);
            float4 ph = ld4(phiA + i0);
            float w0 = fabsf(rh.x * expf(-0.1f * (ph.x + logf(rh.x)))) + 1e-8f;
            float w1 = fabsf(rh.y * expf(-0.1f * (ph.y + logf(rh.y)))) + 1e-8f;
            float w2 = fabsf(rh.z * expf(-0.1f * (ph.z + logf(rh.z)))) + 1e-8f;
            float w3 = fabsf(rh.w * expf(-0.1f * (ph.w + logf(rh.w)))) + 1e-8f;
            float Z = bsum1(w0 + w1 + w2 + w3, red, sl);
            float iZ = 1.0f / Z;
            st4h(rho, i0, make_float4(w0 * iZ, w1 * iZ, w2 * iZ, w3 * iZ));
        }

        // 5 inner MPC gradient steps (up = leray(u) tracked directly)
#pragma unroll 1
        for (int is = 0; is < 5; is++) {
            float4 up4 = ld4(upA + i0);
            float a0 = fabsf(up4.x), a1 = fabsf(up4.y);
            float a2 = fabsf(up4.z), a3 = fabsf(up4.w);
            float lm = fmaxf(fmaxf(a0, a1), fmaxf(a2, a3));
            float lc = (a0 == lm ? 1.0f : 0.0f) + (a1 == lm ? 1.0f : 0.0f)
                     + (a2 == lm ? 1.0f : 0.0f) + (a3 == lm ? 1.0f : 0.0f);
            float nt;
            float m = bmaxcnt1(lm, lc, mred, &nt);
            float dt = 0.4f / (m + 1e-8f);

            float z0 = advect_fwd(r1A, rho, 1.0f, upA, dt, red, sl);
            float z1 = advect_fwd(r2A, r1A, 1.0f / z0, upA, dt, red, sl);
            float z2 = advect_fwd(r3A, r2A, 1.0f / z1, upA, dt, red, sl);
            float dotraw;
            float z3 = advect_fwd_dot(r4A, r3A, 1.0f / z2, upA, vA, dt,
                                      red, red2, sl, &dotraw);

            float dtl = advect_bwd_first(r3A, 1.0f / z2, z3, dotraw, upA, dt,
                                         vA, rbA, abA, ubA);
            dtl += advect_bwd(r2A, 1.0f / z1, r3A, z2, upA, dt, rbA, abA, ubA, red, sl);
            dtl += advect_bwd(r1A, 1.0f / z0, r2A, z1, upA, dt, rbA, abA, ubA, red, sl);
            float dtbar = advect_bwd_last(rho, 1.0f, r1A, z0, upA, dt, dtl,
                                          rbA, abA, ubA, red, red2, sl);

            float mbar = dtbar * (-dt * dt * 2.5f);  // d(dt)/dm = -dt^2/CFL
            {
                float4 ub4 = ld4(ubA + i0);
                float inv_nt = mbar / nt;
                float add0 = (a0 == m) ? inv_nt * ((up4.x > 0.0f) ? 1.0f : -1.0f) : 0.0f;
                float add1 = (a1 == m) ? inv_nt * ((up4.y > 0.0f) ? 1.0f : -1.0f) : 0.0f;
                float add2 = (a2 == m) ? inv_nt * ((up4.z > 0.0f) ? 1.0f : -1.0f) : 0.0f;
                float add3 = (a3 == m) ? inv_nt * ((up4.w > 0.0f) ? 1.0f : -1.0f) : 0.0f;
                st4h(ubA, i0, make_float4(ub4.x + add0, ub4.y + add1,
                                          ub4.z + add2, ub4.w + add3));
            }
            __syncthreads();                    // publish ub before conv reads

            conv2_update(upA, ubA);             // up -= (lr/B)*leray^2(ub)
        }

        // main advect with kappa; up already = leray(u_final)
        {
            float4 up4 = ld4(upA + i0);
            float lm = fmaxf(fmaxf(fabsf(up4.x), fabsf(up4.y)),
                             fmaxf(fabsf(up4.z), fabsf(up4.w)));
            float mm = bmax1(lm, mred);
            float dt = 0.4f / (mm + 1e-8f);
            advect_final(spare, rho, upA, dt, kap, red, sl);
            float* tmp = rho; rho = spare; spare = tmp;
        }
    }

    // rho_f = (rho + 0.1 v) / sum
    {
        float4 rh = ld4(rho + i0);
        float4 v4 = ld4(vA + i0);
        float f0 = rh.x + 0.1f * v4.x, f1 = rh.y + 0.1f * v4.y;
        float f2 = rh.z + 0.1f * v4.z, f3 = rh.w + 0.1f * v4.w;
        float Z = bsum1(f0 + f1 + f2 + f3, red, sl);
        float iZ = 1.0f / Z;
        st4(g_rhof + b * Sc + i0, make_float4(f0 * iZ, f1 * iZ, f2 * iZ, f3 * iZ));
    }
}

// ---------------- epilogue: fused inverse DWT ----------------------------
__global__ void __launch_bounds__(256) out_kernel(const float* __restrict__ bw,
                                                  float* __restrict__ out) {
    int g = blockIdx.x, b = blockIdx.y, tid = threadIdx.x;
    const float* rf = g_rhof + b * Sc;
    float rfA = rf[g];
    float rf3 = rf[256 + g];
    float rf2a = rf[512 + 2 * g], rf2b = rf[512 + 2 * g + 1];
    float rf1_0 = rf[1024 + 4 * g], rf1_1 = rf[1024 + 4 * g + 1];
    float rf1_2 = rf[1024 + 4 * g + 2], rf1_3 = rf[1024 + 4 * g + 3];

    const float C8 = 0.35355339059327376220f;  // 1/(2*sqrt(2))
    float cA = rfA * C8;
    float c3 = rf3 * C8;
    float c2arr[2] = {rf2a * 0.5f, rf2b * 0.5f};
    float c1arr[4] = {rf1_0 * IS2, rf1_1 * IS2, rf1_2 * IS2, rf1_3 * IS2};

    const float4* bw4 = (const float4*)bw;
    float4* o4 = (float4*)(out + ((size_t)b * Sc + 8 * (size_t)g) * Dc);
#pragma unroll
    for (int c = 0; c < 2; c++) {
        int c4 = tid + c * 256;
        float4 b0 = bw4[0 * 512 + c4];
        float4 b1 = bw4[1 * 512 + c4];
        float4 b2 = bw4[2 * 512 + c4];
        float4 b3 = bw4[3 * 512 + c4];
#pragma unroll
        for (int r = 0; r < 8; r++) {
            float s2 = (r < 4) ? 1.0f : -1.0f;
            float s1 = (((r >> 1) & 1) == 0) ? 1.0f : -1.0f;
            float s0 = ((r & 1) == 0) ? 1.0f : -1.0f;
            float k0 = cA;
            float k1 = s2 * c3;
            float k2 = s1 * c2arr[r >> 2];
            float k3 = s0 * c1arr[r >> 1];
            float4 o;
            o.x = k0 * b0.x + k1 * b1.x + k2 * b2.x + k3 * b3.x;
            o.y = k0 * b0.y + k1 * b1.y + k2 * b2.y + k3 * b3.y;
            o.z = k0 * b0.z + k1 * b1.z + k2 * b2.z + k3 * b3.z;
            o.w = k0 * b0.w + k1 * b1.w + k2 * b2.w + k3 * b3.w;
            o4[r * 512 + c4] = o;
        }
    }
}

// ---------------- launch --------------------------------------------------
extern "C" void kernel_launch(void* const* d_in, const int* in_sizes, int n_in,
                              void* d_out, int out_size) {
    const float* x    = (const float*)d_in[0];
    const float* wval = (const float*)d_in[1];
    const float* phi  = (const float*)d_in[2];
    const float* bw   = (const float*)d_in[3];
    float* out = (float*)d_out;

    cudaFuncSetAttribute(sim_kernel, cudaFuncAttributeMaxDynamicSharedMemorySize, SIM_SMEM);

    prep_kernel<<<dim3(256, 8), 256>>>(x, wval);
    sim_kernel<<<8, NTS, SIM_SMEM>>>(phi);
    out_kernel<<<dim3(256, 8), 256>>>(bw, out);
}

// round 12
// speedup vs baseline: 2.3881x; 1.1032x over previous
#include <cuda_runtime.h>
#include <math.h>

#define Sc 2048
#define Dc 2048
#define NTS 512
#define FULLM 0xffffffffu
#define IS2 0.70710678118654752440f
#define HAL 72
#define LD 2192

// ---------------- device scratch ----------------------------------------
__device__ float g_ssq[8 * Sc];   // sum over d of dwt coeff^2
__device__ float g_pt[8 * Sc];    // per-token dot with w_val
__device__ float g_rhof[8 * Sc];  // final rho_f (normalized)

// ---------------- compile-time leray taps --------------------------------
// leray = I - grad1(Jacobi50(div1(.))) : fixed circulant. Computed in double
// at compile time; accessed via constexpr locals so multipliers fold to
// float immediates (FFMA-imm rt=1). No --expt-relaxed-constexpr needed.
struct Taps {
    float k[68];    // leray taps, disp -32..+32 (65 used, pad 68)
    float k2[68];   // 0.0125 * (kl conv kl), disp -32..+32 (65 used, pad 68)
};
__host__ __device__ constexpr Taps make_taps() {
    Taps t = {};
    double p[256] = {};
    double pn[256] = {};
    for (int it = 0; it < 50; it++) {
        for (int i = 0; i < 256; i++) {
            double l = (i > 0) ? p[i - 1] : 0.0;
            double r = (i < 255) ? p[i + 1] : 0.0;
            double bb = (i == 128) ? 1.0 : ((i == 129) ? -1.0 : 0.0);
            pn[i] = 0.5 * (r + l - bb);
        }
        for (int i = 0; i < 256; i++) p[i] = pn[i];
    }
    double kl[103] = {};
    for (int j = 0; j < 103; j++) {
        int i = 77 + j;                      // disp = j - 51
        double del = (i == 128) ? 1.0 : 0.0;
        kl[j] = del - (p[i + 1] - p[i]);
    }
    for (int j = 0; j < 68; j++)
        t.k[j] = (j < 65) ? (float)kl[j + 19] : 0.0f;
    for (int j = 0; j < 68; j++) {
        double s = 0.0;
        if (j < 65) {
            int d = j - 32;
            for (int a = -51; a <= 51; a++) {
                int e = d - a;
                if (e >= -51 && e <= 51) s += kl[a + 51] * kl[e + 51];
            }
            s *= 0.0125;                     // INNER_LR / B folded in
        }
        t.k2[j] = (float)s;
    }
    return t;
}

// ---------------- prep: DWT energies + per-token dots --------------------
__global__ void __launch_bounds__(256) prep_kernel(const float* __restrict__ x,
                                                   const float* __restrict__ wval) {
    int g = blockIdx.x;   // 0..255
    int b = blockIdx.y;   // 0..7
    int tid = threadIdx.x;
    const float4* xv = (const float4*)(x + ((size_t)b * Sc + 8 * (size_t)g) * Dc);
    const float4* wv = (const float4*)wval;

    float acc[16];
#pragma unroll
    for (int i = 0; i < 16; i++) acc[i] = 0.0f;

#pragma unroll
    for (int c = 0; c < 2; c++) {
        int c4 = tid + c * 256;
        float4 w4 = wv[c4];
        float xr[4][8];
#pragma unroll
        for (int r = 0; r < 8; r++) {
            float4 q = xv[r * 512 + c4];
            xr[0][r] = q.x; xr[1][r] = q.y; xr[2][r] = q.z; xr[3][r] = q.w;
        }
        float wc[4] = {w4.x, w4.y, w4.z, w4.w};
#pragma unroll
        for (int cc = 0; cc < 4; cc++) {
            const float* X = xr[cc];
            float w = wc[cc];
#pragma unroll
            for (int r = 0; r < 8; r++) acc[8 + r] += X[r] * w;
            float a10 = (X[0] + X[1]) * IS2, d10 = (X[0] - X[1]) * IS2;
            float a11 = (X[2] + X[3]) * IS2, d11 = (X[2] - X[3]) * IS2;
            float a12 = (X[4] + X[5]) * IS2, d12 = (X[4] - X[5]) * IS2;
            float a13 = (X[6] + X[7]) * IS2, d13 = (X[6] - X[7]) * IS2;
            float a20 = (a10 + a11) * IS2, d20 = (a10 - a11) * IS2;
            float a21 = (a12 + a13) * IS2, d21 = (a12 - a13) * IS2;
            float a3 = (a20 + a21) * IS2, d3 = (a20 - a21) * IS2;
            acc[0] += a3 * a3;   acc[1] += d3 * d3;
            acc[2] += d20 * d20; acc[3] += d21 * d21;
            acc[4] += d10 * d10; acc[5] += d11 * d11;
            acc[6] += d12 * d12; acc[7] += d13 * d13;
        }
    }
#pragma unroll
    for (int off = 16; off; off >>= 1)
#pragma unroll
        for (int j = 0; j < 16; j++) acc[j] += __shfl_xor_sync(FULLM, acc[j], off);

    __shared__ float sred[8 * 16];
    int lane = tid & 31, wid = tid >> 5;
    if (lane == 0)
#pragma unroll
        for (int j = 0; j < 16; j++) sred[wid * 16 + j] = acc[j];
    __syncthreads();
    if (tid < 16) {
        float s = 0.0f;
#pragma unroll
        for (int w = 0; w < 8; w++) s += sred[w * 16 + tid];
        int base = b * Sc;
        if (tid < 8) {
            int idx;
            if (tid == 0) idx = g;
            else if (tid == 1) idx = 256 + g;
            else if (tid < 4) idx = 512 + 2 * g + (tid - 2);
            else idx = 1024 + 4 * g + (tid - 4);
            g_ssq[base + idx] = s;
        } else {
            g_pt[base + 8 * g + (tid - 8)] = s;
        }
    }
}

// ---------------- small helpers ------------------------------------------
__device__ __forceinline__ float4 ld4(const float* p) { return *(const float4*)p; }
__device__ __forceinline__ void st4(float* p, float4 v) { *(float4*)p = v; }
__device__ __forceinline__ void st4h(float* A, int i0, float4 v) {
    *(float4*)(A + i0) = v;
    if (i0 < HAL) *(float4*)(A + i0 + Sc) = v;
    if (i0 >= Sc - HAL) *(float4*)(A + i0 - Sc) = v;
}
__device__ __forceinline__ void sth(float* A, int i, float v) {
    A[i] = v;
    if (i < HAL) A[i + Sc] = v;
    if (i >= Sc - HAL) A[i - Sc] = v;
}

// ------------- single-barrier reductions (512 thr, 16 warps) -------------
__device__ __forceinline__ float bsum1(float v, float* red, int& sl) {
#pragma unroll
    for (int o = 16; o; o >>= 1) v += __shfl_xor_sync(FULLM, v, o);
    int lane = threadIdx.x & 31, wid = threadIdx.x >> 5;
    if (lane == 0) red[sl * 16 + wid] = v;
    __syncthreads();
    float s = 0.0f;
    const float* rr = red + sl * 16;
#pragma unroll
    for (int w = 0; w < 16; w++) s += rr[w];
    sl ^= 1;
    return s;
}

// dual sum in one barrier: second sum goes to red2 (16 floats)
__device__ __forceinline__ float bsum2(float v, float v2, float* red, float* red2,
                                       int& sl, float* out2) {
#pragma unroll
    for (int o = 16; o; o >>= 1) {
        v += __shfl_xor_sync(FULLM, v, o);
        v2 += __shfl_xor_sync(FULLM, v2, o);
    }
    int lane = threadIdx.x & 31, wid = threadIdx.x >> 5;
    if (lane == 0) { red[sl * 16 + wid] = v; red2[wid] = v2; }
    __syncthreads();
    float s = 0.0f, s2 = 0.0f;
    const float* rr = red + sl * 16;
#pragma unroll
    for (int w = 0; w < 16; w++) { s += rr[w]; s2 += red2[w]; }
    sl ^= 1;
    *out2 = s2;
    return s;
}

// shfl-reduce + slot write WITHOUT barrier (published by a later barrier)
__device__ __forceinline__ void partial_store(float p, float* red, int sl) {
#pragma unroll
    for (int o = 16; o; o >>= 1) p += __shfl_xor_sync(FULLM, p, o);
    int lane = threadIdx.x & 31, wid = threadIdx.x >> 5;
    if (lane == 0) red[sl * 16 + wid] = p;
}
// read a published slot (caller must have barriered); flips slot
__device__ __forceinline__ float partial_read(const float* red, int& sl) {
    float s = 0.0f;
    const float* rr = red + sl * 16;
#pragma unroll
    for (int w = 0; w < 16; w++) s += rr[w];
    sl ^= 1;
    return s;
}

__device__ __forceinline__ float bmax1(float v, float* mred) {
#pragma unroll
    for (int o = 16; o; o >>= 1) v = fmaxf(v, __shfl_xor_sync(FULLM, v, o));
    int lane = threadIdx.x & 31, wid = threadIdx.x >> 5;
    if (lane == 0) mred[wid] = v;
    __syncthreads();
    float m = mred[0];
#pragma unroll
    for (int w = 1; w < 16; w++) m = fmaxf(m, mred[w]);
    return m;
}

// fused (max, tie-count) reduction, one barrier
__device__ __forceinline__ float bmaxcnt1(float m, float c, float* mred, float* cnt_out) {
#pragma unroll
    for (int o = 16; o; o >>= 1) {
        float m2 = __shfl_xor_sync(FULLM, m, o);
        float c2 = __shfl_xor_sync(FULLM, c, o);
        if (m2 > m) { m = m2; c = c2; }
        else if (m2 == m) { c += c2; }
    }
    int lane = threadIdx.x & 31, wid = threadIdx.x >> 5;
    if (lane == 0) { mred[wid] = m; mred[16 + wid] = c; }
    __syncthreads();
    float M = mred[0];
#pragma unroll
    for (int w = 1; w < 16; w++) M = fmaxf(M, mred[w]);
    float C = 0.0f;
#pragma unroll
    for (int w = 0; w < 16; w++) C += (mred[w] == M) ? mred[16 + w] : 0.0f;
    *cnt_out = C;
    return M;
}

// ---------------- leray: 65-tap conv, immediate taps (init only) ---------
__device__ __forceinline__ void conv_leray(float* __restrict__ dst,
                                           const float* __restrict__ src) {
    constexpr Taps TAPS = make_taps();
    int i0 = 4 * threadIdx.x;
    const float* S = src + i0 - 32;
    float4 cur = ld4(S);
    float a0 = 0.0f, a1 = 0.0f, a2 = 0.0f, a3 = 0.0f;
#pragma unroll
    for (int m = 0; m < 17; m++) {
        float4 nxt = ld4(S + 4 * m + 4);
        const float kx = TAPS.k[4 * m], ky = TAPS.k[4 * m + 1];
        const float kz = TAPS.k[4 * m + 2], kw = TAPS.k[4 * m + 3];
        a0 += kx * cur.x + ky * cur.y + kz * cur.z + kw * cur.w;
        a1 += kx * cur.y + ky * cur.z + kz * cur.w + kw * nxt.x;
        a2 += kx * cur.z + ky * cur.w + kz * nxt.x + kw * nxt.y;
        a3 += kx * cur.w + ky * nxt.x + kz * nxt.y + kw * nxt.z;
        cur = nxt;
    }
    st4h(dst, i0, make_float4(a0, a1, a2, a3));
    __syncthreads();
}

// ------- fused: up -= (lr/B)*leray^2(ub), 65-tap imm conv, no barrier ----
__device__ __forceinline__ void conv2_update(float* __restrict__ up,
                                             const float* __restrict__ ub) {
    constexpr Taps TAPS = make_taps();
    int i0 = 4 * threadIdx.x;
    const float* S = ub + i0 - 32;
    float4 cur = ld4(S);
    float a0 = 0.0f, a1 = 0.0f, a2 = 0.0f, a3 = 0.0f;
#pragma unroll
    for (int m = 0; m < 17; m++) {
        float4 nxt = ld4(S + 4 * m + 4);
        const float kx = TAPS.k2[4 * m], ky = TAPS.k2[4 * m + 1];
        const float kz = TAPS.k2[4 * m + 2], kw = TAPS.k2[4 * m + 3];
        a0 += kx * cur.x + ky * cur.y + kz * cur.z + kw * cur.w;
        a1 += kx * cur.y + ky * cur.z + kz * cur.w + kw * nxt.x;
        a2 += kx * cur.z + ky * cur.w + kz * nxt.x + kw * nxt.y;
        a3 += kx * cur.w + ky * nxt.x + kz * nxt.y + kw * nxt.z;
        cur = nxt;
    }
    float4 u = ld4(up + i0);
    st4h(up, i0, make_float4(u.x - a0, u.y - a1, u.z - a2, u.w - a3));
}

// ---- forward advect: store RAW y, one barrier, return Z -----------------
__device__ __forceinline__ float advect_fwd(float* __restrict__ dst,
                                            const float* __restrict__ r, float iZr,
                                            const float uv[5],
                                            float dt, float* red, int& sl) {
    int i0 = 4 * threadIdx.x;
    float4 r0 = ld4(r + i0);
    float rv[6] = {r[i0 - 1] * iZr, r0.x * iZr, r0.y * iZr, r0.z * iZr, r0.w * iZr,
                   r[i0 + 4] * iZr};
    float F[5];
#pragma unroll
    for (int k = 0; k < 5; k++)
        F[k] = uv[k] > 0.0f ? uv[k] * rv[k] : uv[k] * rv[k + 1];
    float y[4], part = 0.0f;
#pragma unroll
    for (int e = 0; e < 4; e++) {
        y[e] = fabsf(rv[e + 1] - dt * (F[e + 1] - F[e])) + 1e-8f;
        part += y[e];
    }
    st4h(dst, i0, make_float4(y[0], y[1], y[2], y[3]));
    return bsum1(part, red, sl);
}

// ---- forward advect for r4: also reduces dot((1-v), y_raw) --------------
__device__ __forceinline__ float advect_fwd_dot(float* __restrict__ dst,
                                                const float* __restrict__ r, float iZr,
                                                const float uv[5],
                                                const float* __restrict__ vA,
                                                float dt, float* red, float* red2,
                                                int& sl, float* dotraw_out) {
    int i0 = 4 * threadIdx.x;
    float4 r0 = ld4(r + i0);
    float rv[6] = {r[i0 - 1] * iZr, r0.x * iZr, r0.y * iZr, r0.z * iZr, r0.w * iZr,
                   r[i0 + 4] * iZr};
    float F[5];
#pragma unroll
    for (int k = 0; k < 5; k++)
        F[k] = uv[k] > 0.0f ? uv[k] * rv[k] : uv[k] * rv[k + 1];
    float4 v4 = ld4(vA + i0);
    float vb[4] = {1.0f - v4.x, 1.0f - v4.y, 1.0f - v4.z, 1.0f - v4.w};
    float y[4], part = 0.0f, part2 = 0.0f;
#pragma unroll
    for (int e = 0; e < 4; e++) {
        y[e] = fabsf(rv[e + 1] - dt * (F[e + 1] - F[e])) + 1e-8f;
        part += y[e];
        part2 += vb[e] * y[e];
    }
    st4h(dst, i0, make_float4(y[0], y[1], y[2], y[3]));
    return bsum2(part, part2, red, red2, sl, dotraw_out);
}

// ---- final outer advect (with kappa), stores NORMALIZED -----------------
__device__ __forceinline__ void advect_final(float* __restrict__ dst,
                                             const float* __restrict__ r,  // normalized
                                             const float* __restrict__ u,
                                             float dt, float kap, float* red, int& sl) {
    int i0 = 4 * threadIdx.x;
    float4 r0 = ld4(r + i0);
    float rv[6] = {r[i0 - 1], r0.x, r0.y, r0.z, r0.w, r[i0 + 4]};
    float4 u0 = ld4(u + i0);
    float uv[5] = {u[i0 - 1], u0.x, u0.y, u0.z, u0.w};
    float F[5];
#pragma unroll
    for (int k = 0; k < 5; k++)
        F[k] = uv[k] > 0.0f ? uv[k] * rv[k] : uv[k] * rv[k + 1];
    float y[4], part = 0.0f;
#pragma unroll
    for (int e = 0; e < 4; e++) {
        float a = rv[e + 1] - dt * (F[e + 1] - F[e])
                + kap * dt * (rv[e + 2] + rv[e] - 2.0f * rv[e + 1]);
        y[e] = fabsf(a) + 1e-8f;
        part += y[e];
    }
    float Z = bsum1(part, red, sl);
    float iZ = 1.0f / Z;
    st4h(dst, i0, make_float4(y[0] * iZ, y[1] * iZ, y[2] * iZ, y[3] * iZ));
}

// ---- FIRST backward step (t=4): rb=(1-v), dot from fwd; SETS ub ---------
// Tail: computes rb_3 (regs) and the next dot partial, writes red[sl]
// (published by the NEXT step's entry barrier).
__device__ __forceinline__ float bwd_first(const float* __restrict__ rt, float iZt,
                                           float Zn, float dotraw,
                                           const float uv[5], float dt,
                                           const float* __restrict__ vA,
                                           float* __restrict__ abA,
                                           float rb[4], float ub[4],
                                           float* red, int sl) {
    int i0 = 4 * threadIdx.x;
    float iZn = 1.0f / Zn;
    float dot = dotraw * iZn;

    float4 r0 = ld4(rt + i0);
    float rr[4] = {r0.x, r0.y, r0.z, r0.w};                 // raw, for next dot
    float rv[6] = {rt[i0 - 1] * iZt, r0.x * iZt, r0.y * iZt, r0.z * iZt, r0.w * iZt,
                   rt[i0 + 4] * iZt};
    float F[5];
#pragma unroll
    for (int k = 0; k < 5; k++)
        F[k] = uv[k] > 0.0f ? uv[k] * rv[k] : uv[k] * rv[k + 1];

    float4 v4 = ld4(vA + i0);
    float rbl[4] = {1.0f - v4.x, 1.0f - v4.y, 1.0f - v4.z, 1.0f - v4.w};
    float ab[4], dtl = 0.0f;
#pragma unroll
    for (int e = 0; e < 4; e++) {
        float a = rv[e + 1] - dt * (F[e + 1] - F[e]);
        float s = (a > 0.0f) ? 1.0f : ((a < 0.0f) ? -1.0f : 0.0f);
        ab[e] = (rbl[e] - dot) * iZn * s;
        dtl -= ab[e] * (F[e + 1] - F[e]);
    }
    st4h(abA, i0, make_float4(ab[0], ab[1], ab[2], ab[3]));
    __syncthreads();

    float abv[6] = {abA[i0 - 1], ab[0], ab[1], ab[2], ab[3], abA[i0 + 4]};
    float Fb[5];
#pragma unroll
    for (int k = 0; k < 5; k++)
        Fb[k] = -dt * (abv[k] - abv[k + 1]);
#pragma unroll
    for (int e = 0; e < 4; e++) {
        ub[e] = Fb[e + 1] * (uv[e + 1] > 0.0f ? rv[e + 1] : rv[e + 2]);   // SET
        rb[e] = ab[e] + (uv[e + 1] > 0.0f ? Fb[e + 1] * uv[e + 1] : 0.0f)
                      + (uv[e] > 0.0f ? 0.0f : Fb[e] * uv[e]);
    }
    partial_store(rb[0] * rr[0] + rb[1] * rr[1] + rb[2] * rr[2] + rb[3] * rr[3],
                  red, sl);
    return dtl;
}

// ---- middle backward step: entry barrier publishes the pending partial --
__device__ __forceinline__ float bwd_mid(const float* __restrict__ rt, float iZt,
                                         float Zn,
                                         const float uv[5], float dt,
                                         float* __restrict__ abA,
                                         float rb[4], float ub[4],
                                         float* red, int& sl) {
    int i0 = 4 * threadIdx.x;
    __syncthreads();                           // publish red partial + abA WAR fence
    float dotraw = partial_read(red, sl);
    float iZn = 1.0f / Zn;
    float dot = dotraw * iZn;

    float4 r0 = ld4(rt + i0);
    float rr[4] = {r0.x, r0.y, r0.z, r0.w};
    float rv[6] = {rt[i0 - 1] * iZt, r0.x * iZt, r0.y * iZt, r0.z * iZt, r0.w * iZt,
                   rt[i0 + 4] * iZt};
    float F[5];
#pragma unroll
    for (int k = 0; k < 5; k++)
        F[k] = uv[k] > 0.0f ? uv[k] * rv[k] : uv[k] * rv[k + 1];

    float ab[4], dtl = 0.0f;
#pragma unroll
    for (int e = 0; e < 4; e++) {
        float a = rv[e + 1] - dt * (F[e + 1] - F[e]);
        float s = (a > 0.0f) ? 1.0f : ((a < 0.0f) ? -1.0f : 0.0f);
        ab[e] = (rb[e] - dot) * iZn * s;
        dtl -= ab[e] * (F[e + 1] - F[e]);
    }
    st4h(abA, i0, make_float4(ab[0], ab[1], ab[2], ab[3]));
    __syncthreads();

    float abv[6] = {abA[i0 - 1], ab[0], ab[1], ab[2], ab[3], abA[i0 + 4]};
    float Fb[5];
#pragma unroll
    for (int k = 0; k < 5; k++)
        Fb[k] = -dt * (abv[k] - abv[k + 1]);
#pragma unroll
    for (int e = 0; e < 4; e++) {
        ub[e] += Fb[e + 1] * (uv[e + 1] > 0.0f ? rv[e + 1] : rv[e + 2]);
        rb[e] = ab[e] + (uv[e + 1] > 0.0f ? Fb[e + 1] * uv[e + 1] : 0.0f)
                      + (uv[e] > 0.0f ? 0.0f : Fb[e] * uv[e]);
    }
    partial_store(rb[0] * rr[0] + rb[1] * rr[1] + rb[2] * rr[2] + rb[3] * rr[3],
                  red, sl);
    return dtl;
}

// ---- LAST backward step: dtbar fused into the abA-publish barrier -------
__device__ __forceinline__ float bwd_last(const float* __restrict__ rt,
                                          float Zn,
                                          const float uv[5], float dt, float dtl_in,
                                          float* __restrict__ abA,
                                          float rb[4], float ub[4],
                                          float* red, float* red2, int& sl) {
    int i0 = 4 * threadIdx.x;
    __syncthreads();                           // publish red partial + abA WAR fence
    float dotraw = partial_read(red, sl);
    float iZn = 1.0f / Zn;
    float dot = dotraw * iZn;

    float4 r0 = ld4(rt + i0);
    float rv[6] = {rt[i0 - 1], r0.x, r0.y, r0.z, r0.w, rt[i0 + 4]};  // iZt = 1
    float F[5];
#pragma unroll
    for (int k = 0; k < 5; k++)
        F[k] = uv[k] > 0.0f ? uv[k] * rv[k] : uv[k] * rv[k + 1];

    float ab[4], dtl = dtl_in;
#pragma unroll
    for (int e = 0; e < 4; e++) {
        float a = rv[e + 1] - dt * (F[e + 1] - F[e]);
        float s = (a > 0.0f) ? 1.0f : ((a < 0.0f) ? -1.0f : 0.0f);
        ab[e] = (rb[e] - dot) * iZn * s;
        dtl -= ab[e] * (F[e + 1] - F[e]);
    }
    st4h(abA, i0, make_float4(ab[0], ab[1], ab[2], ab[3]));
    // fuse dtbar reduction into the abA-publish barrier
    float t = dtl;
#pragma unroll
    for (int o = 16; o; o >>= 1) t += __shfl_xor_sync(FULLM, t, o);
    int lane = threadIdx.x & 31, wid = threadIdx.x >> 5;
    if (lane == 0) red2[wid] = t;
    __syncthreads();
    float dtbar = 0.0f;
#pragma unroll
    for (int w = 0; w < 16; w++) dtbar += red2[w];

    float abv[6] = {abA[i0 - 1], ab[0], ab[1], ab[2], ab[3], abA[i0 + 4]};
    float Fb[5];
#pragma unroll
    for (int k = 0; k < 5; k++)
        Fb[k] = -dt * (abv[k] - abv[k + 1]);
#pragma unroll
    for (int e = 0; e < 4; e++)
        ub[e] += Fb[e + 1] * (uv[e + 1] > 0.0f ? rv[e + 1] : rv[e + 2]);
    return dtbar;
}

// ---------------- main simulation: one CTA per batch ---------------------
#define SIM_SMEM ((2128 + 11 * LD) * 4)

__global__ void __launch_bounds__(NTS, 1) sim_kernel(const float* __restrict__ phi_g) {
    extern __shared__ float sm[];
    float* red  = sm;          // 32 (2 slots x 16)
    float* red2 = sm + 32;     // 16 (secondary fused sums)
    float* mred = sm + 48;     // 32 (max + cnt)
    float* phiA = sm + 80;     // 2048
    float* arr  = sm + 2128;   // 11 x LD haloed arrays
    float* vA   = arr + 0 * LD + HAL;
    float* up0A = arr + 1 * LD + HAL;
    float* upA  = arr + 2 * LD + HAL;
    float* rhoA = arr + 3 * LD + HAL;
    float* spA  = arr + 4 * LD + HAL;
    float* r1A  = arr + 5 * LD + HAL;
    float* r2A  = arr + 6 * LD + HAL;
    float* r3A  = arr + 7 * LD + HAL;
    float* r4A  = arr + 8 * LD + HAL;
    float* abA  = arr + 9 * LD + HAL;
    float* ubA  = arr + 10 * LD + HAL;

    int b = blockIdx.x;
    int tid = threadIdx.x;
    int i0 = 4 * tid;
    int sl = 0;

    st4(phiA + i0, ld4(phi_g + i0));

    // rho = normalize(sqrt(ssq)+eps)
    {
        float4 s4 = ld4(g_ssq + b * Sc + i0);
        float y0 = sqrtf(s4.x) + 1e-8f, y1 = sqrtf(s4.y) + 1e-8f;
        float y2 = sqrtf(s4.z) + 1e-8f, y3 = sqrtf(s4.w) + 1e-8f;
        float Z = bsum1(y0 + y1 + y2 + y3, red, sl);
        float iZ = 1.0f / Z;
        st4h(rhoA, i0, make_float4(y0 * iZ, y1 * iZ, y2 * iZ, y3 * iZ));
    }

    // v = normalize(sqrt(D)*|dwt(pt)|+eps)
    st4(r1A + i0, ld4(g_pt + b * Sc + i0));
    __syncthreads();
#pragma unroll
    for (int s = 0; s < 2; s++) {           // level 1
        int j = 2 * tid + s;
        float e = r1A[2 * j], o = r1A[2 * j + 1];
        sth(vA, 1024 + j, (e - o) * IS2);
        r2A[j] = (e + o) * IS2;
    }
    __syncthreads();
    {                                       // level 2
        float e = r2A[2 * tid], o = r2A[2 * tid + 1];
        sth(vA, 512 + tid, (e - o) * IS2);
        r1A[tid] = (e + o) * IS2;
    }
    __syncthreads();
    if (tid < 256) {                        // level 3
        float e = r1A[2 * tid], o = r1A[2 * tid + 1];
        sth(vA, 256 + tid, (e - o) * IS2);
        sth(vA, tid, (e + o) * IS2);
    }
    __syncthreads();
    {
        float4 v4 = ld4(vA + i0);
        float y0 = 45.254833995939045f * fabsf(v4.x) + 1e-8f;
        float y1 = 45.254833995939045f * fabsf(v4.y) + 1e-8f;
        float y2 = 45.254833995939045f * fabsf(v4.z) + 1e-8f;
        float y3 = 45.254833995939045f * fabsf(v4.w) + 1e-8f;
        float Z = bsum1(y0 + y1 + y2 + y3, red, sl);
        float iZ = 1.0f / Z;
        st4h(vA, i0, make_float4(y0 * iZ, y1 * iZ, y2 * iZ, y3 * iZ));
        __syncthreads();
    }

    // up0 = leray(grad1(v)) — outer-invariant
    {
        float4 v0 = ld4(vA + i0);
        float v4n = vA[i0 + 4];
        st4h(ubA, i0, make_float4(v0.y - v0.x, v0.z - v0.y, v0.w - v0.z, v4n - v0.w));
        __syncthreads();
        conv_leray(up0A, ubA);
    }

    float* rho = rhoA;
    float* spare = spA;

#pragma unroll 1
    for (int k = 0; k < 3; k++) {
        float kap = (k == 0) ? 0.01f : ((k == 1) ? 0.005f : 0.0f);

        // up <- up0 copy (raw-aligned). The reaction's bsum1 barrier orders
        // these stores before the inner loop's reads.
        for (int q = 4 * tid; q < LD; q += 4 * NTS)
            st4(arr + 2 * LD + q, ld4(arr + 1 * LD + q));

        // reaction (1 mirror-descent step); stores normalized rho
        {
            float4 rh = ld4(rho + i0);
            float4 ph = ld4(phiA + i0);
            float w0 = fabsf(rh.x * expf(-0.1f * (ph.x + logf(rh.x)))) + 1e-8f;
            float w1 = fabsf(rh.y * expf(-0.1f * (ph.y + logf(rh.y)))) + 1e-8f;
            float w2 = fabsf(rh.z * expf(-0.1f * (ph.z + logf(rh.z)))) + 1e-8f;
            float w3 = fabsf(rh.w * expf(-0.1f * (ph.w + logf(rh.w)))) + 1e-8f;
            float Z = bsum1(w0 + w1 + w2 + w3, red, sl);
            float iZ = 1.0f / Z;
            st4h(rho, i0, make_float4(w0 * iZ, w1 * iZ, w2 * iZ, w3 * iZ));
        }

        // 5 inner MPC gradient steps (up = leray(u) tracked directly)
#pragma unroll 1
        for (int is = 0; is < 5; is++) {
            float4 up4 = ld4(upA + i0);      // own values (safe pre-barrier)
            float a0 = fabsf(up4.x), a1 = fabsf(up4.y);
            float a2 = fabsf(up4.z), a3 = fabsf(up4.w);
            float lm = fmaxf(fmaxf(a0, a1), fmaxf(a2, a3));
            float lc = (a0 == lm ? 1.0f : 0.0f) + (a1 == lm ? 1.0f : 0.0f)
                     + (a2 == lm ? 1.0f : 0.0f) + (a3 == lm ? 1.0f : 0.0f);
            float nt;
            float m = bmaxcnt1(lm, lc, mred, &nt);   // BARRIER (publishes upA)
            float dt = 0.4f / (m + 1e-8f);

            // velocity window hoisted once per inner step (post-barrier)
            float uv[5] = {upA[i0 - 1], up4.x, up4.y, up4.z, up4.w};

            float z0 = advect_fwd(r1A, rho, 1.0f, uv, dt, red, sl);
            float z1 = advect_fwd(r2A, r1A, 1.0f / z0, uv, dt, red, sl);
            float z2 = advect_fwd(r3A, r2A, 1.0f / z1, uv, dt, red, sl);
            float dotraw;
            float z3 = advect_fwd_dot(r4A, r3A, 1.0f / z2, uv, vA, dt,
                                      red, red2, sl, &dotraw);

            float rb[4], ub[4];
            float dtl = bwd_first(r3A, 1.0f / z2, z3, dotraw, uv, dt,
                                  vA, abA, rb, ub, red, sl);
            dtl += bwd_mid(r2A, 1.0f / z1, z2, uv, dt, abA, rb, ub, red, sl);
            dtl += bwd_mid(r1A, 1.0f / z0, z1, uv, dt, abA, rb, ub, red, sl);
            float dtbar = bwd_last(rho, z0, uv, dt, dtl, abA, rb, ub,
                                   red, red2, sl);

            float mbar = dtbar * (-dt * dt * 2.5f);  // d(dt)/dm = -dt^2/CFL
            {
                float inv_nt = mbar / nt;
                ub[0] += (a0 == m) ? inv_nt * ((up4.x > 0.0f) ? 1.0f : -1.0f) : 0.0f;
                ub[1] += (a1 == m) ? inv_nt * ((up4.y > 0.0f) ? 1.0f : -1.0f) : 0.0f;
                ub[2] += (a2 == m) ? inv_nt * ((up4.z > 0.0f) ? 1.0f : -1.0f) : 0.0f;
                ub[3] += (a3 == m) ? inv_nt * ((up4.w > 0.0f) ? 1.0f : -1.0f) : 0.0f;
                st4h(ubA, i0, make_float4(ub[0], ub[1], ub[2], ub[3]));
            }
            __syncthreads();                    // publish ub before conv reads

            conv2_update(upA, ubA);             // up -= (lr/B)*leray^2(ub)
        }

        // main advect with kappa; up already = leray(u_final)
        {
            float4 up4 = ld4(upA + i0);
            float lm = fmaxf(fmaxf(fabsf(up4.x), fabsf(up4.y)),
                             fmaxf(fabsf(up4.z), fabsf(up4.w)));
            float mm = bmax1(lm, mred);
            float dt = 0.4f / (mm + 1e-8f);
            advect_final(spare, rho, upA, dt, kap, red, sl);
            float* tmp = rho; rho = spare; spare = tmp;
        }
    }

    // rho_f = (rho + 0.1 v) / sum
    {
        float4 rh = ld4(rho + i0);
        float4 v4 = ld4(vA + i0);
        float f0 = rh.x + 0.1f * v4.x, f1 = rh.y + 0.1f * v4.y;
        float f2 = rh.z + 0.1f * v4.z, f3 = rh.w + 0.1f * v4.w;
        float Z = bsum1(f0 + f1 + f2 + f3, red, sl);
        float iZ = 1.0f / Z;
        st4(g_rhof + b * Sc + i0, make_float4(f0 * iZ, f1 * iZ, f2 * iZ, f3 * iZ));
    }
}

// ---------------- epilogue: fused inverse DWT ----------------------------
__global__ void __launch_bounds__(256) out_kernel(const float* __restrict__ bw,
                                                  float* __restrict__ out) {
    int g = blockIdx.x, b = blockIdx.y, tid = threadIdx.x;
    const float* rf = g_rhof + b * Sc;
    float rfA = rf[g];
    float rf3 = rf[256 + g];
    float rf2a = rf[512 + 2 * g], rf2b = rf[512 + 2 * g + 1];
    float rf1_0 = rf[1024 + 4 * g], rf1_1 = rf[1024 + 4 * g + 1];
    float rf1_2 = rf[1024 + 4 * g + 2], rf1_3 = rf[1024 + 4 * g + 3];

    const float C8 = 0.35355339059327376220f;  // 1/(2*sqrt(2))
    float cA = rfA * C8;
    float c3 = rf3 * C8;
    float c2arr[2] = {rf2a * 0.5f, rf2b * 0.5f};
    float c1arr[4] = {rf1_0 * IS2, rf1_1 * IS2, rf1_2 * IS2, rf1_3 * IS2};

    const float4* bw4 = (const float4*)bw;
    float4* o4 = (float4*)(out + ((size_t)b * Sc + 8 * (size_t)g) * Dc);
#pragma unroll
    for (int c = 0; c < 2; c++) {
        int c4 = tid + c * 256;
        float4 b0 = bw4[0 * 512 + c4];
        float4 b1 = bw4[1 * 512 + c4];
        float4 b2 = bw4[2 * 512 + c4];
        float4 b3 = bw4[3 * 512 + c4];
#pragma unroll
        for (int r = 0; r < 8; r++) {
            float s2 = (r < 4) ? 1.0f : -1.0f;
            float s1 = (((r >> 1) & 1) == 0) ? 1.0f : -1.0f;
            float s0 = ((r & 1) == 0) ? 1.0f : -1.0f;
            float k0 = cA;
            float k1 = s2 * c3;
            float k2 = s1 * c2arr[r >> 2];
            float k3 = s0 * c1arr[r >> 1];
            float4 o;
            o.x = k0 * b0.x + k1 * b1.x + k2 * b2.x + k3 * b3.x;
            o.y = k0 * b0.y + k1 * b1.y + k2 * b2.y + k3 * b3.y;
            o.z = k0 * b0.z + k1 * b1.z + k2 * b2.z + k3 * b3.z;
            o.w = k0 * b0.w + k1 * b1.w + k2 * b2.w + k3 * b3.w;
            o4[r * 512 + c4] = o;
        }
    }
}

// ---------------- launch --------------------------------------------------
extern "C" void kernel_launch(void* const* d_in, const int* in_sizes, int n_in,
                              void* d_out, int out_size) {
    const float* x    = (const float*)d_in[0];
    const float* wval = (const float*)d_in[1];
    const float* phi  = (const float*)d_in[2];
    const float* bw   = (const float*)d_in[3];
    float* out = (float*)d_out;

    cudaFuncSetAttribute(sim_kernel, cudaFuncAttributeMaxDynamicSharedMemorySize, SIM_SMEM);

    prep_kernel<<<dim3(256, 8), 256>>>(x, wval);
    sim_kernel<<<8, NTS, SIM_SMEM>>>(phi);
    out_kernel<<<dim3(256, 8), 256>>>(bw, out);
}